// round 10
// baseline (speedup 1.0000x reference)
#include <cuda_runtime.h>
#include <cuda_fp16.h>
#include <cstdint>
#include <cmath>

#define BATCH 32768
#define HDIM  512
#define NL    5

// ---------------- static device buffers ----------------
#define S2E_SZ (512*512)
#define TF_SZ  (512*1024)
#define S2E_OFF 0
#define TF_OFF  (S2E_OFF + 5*S2E_SZ)
#define FG_OFF  (TF_OFF  + 5*TF_SZ)
#define FW_OFF  (FG_OFF  + 5*S2E_SZ)
#define WG_OFF  (FW_OFF  + 5*TF_SZ)
#define H1_OFF  (WG_OFF  + 5*S2E_SZ)
#define WP_TOTAL (H1_OFF + 4*S2E_SZ)

__device__ __half g_WP[WP_TOTAL];
// per row: [sh_h(512) e_h f_h w_h | (unused) e_l f_l w_l] -> 4096 halves
__device__ __half g_MEGA[(size_t)BATCH * 4096];
__device__ __half g_SCRATCH[(size_t)BATCH * 512];   // fm/wm hi only
__device__ __half g_HEADH[(size_t)4 * BATCH * 512]; // head hiddens hi only

struct Bias4 { const float* p[4]; };

// ---------------- helpers ----------------
__device__ __forceinline__ void cp16s(uint32_t sa, const void* g) {
    asm volatile("cp.async.cg.shared.global [%0], [%1], 16;" :: "r"(sa), "l"(g));
}
__device__ __forceinline__ void ldmx4(uint32_t addr, uint32_t& r0, uint32_t& r1, uint32_t& r2, uint32_t& r3) {
    asm volatile("ldmatrix.sync.aligned.m8n8.x4.shared.b16 {%0,%1,%2,%3}, [%4];"
        : "=r"(r0), "=r"(r1), "=r"(r2), "=r"(r3) : "r"(addr));
}
#define MMA16(acc, a0,a1,a2,a3, b0,b1) \
    asm volatile("mma.sync.aligned.m16n8k16.row.col.f32.f16.f16.f32 " \
        "{%0,%1,%2,%3},{%4,%5,%6,%7},{%8,%9},{%0,%1,%2,%3};" \
        : "+f"((acc)[0]), "+f"((acc)[1]), "+f"((acc)[2]), "+f"((acc)[3]) \
        : "r"(a0), "r"(a1), "r"(a2), "r"(a3), "r"(b0), "r"(b1))

// ---------------- setup kernels ----------------
__global__ void split_inputs_kernel(const float* __restrict__ sh, const float* __restrict__ e,
                                    const float* __restrict__ f,  const float* __restrict__ w) {
    int idx = blockIdx.x * 256 + threadIdx.x;
    if (idx >= BATCH * HDIM) return;
    int row = idx >> 9, k = idx & 511;
    __half* m = g_MEGA + (size_t)row * 4096;
    float v; __half h;
    v = sh[idx]; m[k] = __float2half(v);   // sh_lo never read -> not stored
    v = e[idx];  h = __float2half(v); m[512 + k]  = h; m[2560 + k] = __float2half(v - __half2float(h));
    v = f[idx];  h = __float2half(v); m[1024 + k] = h; m[3072 + k] = __float2half(v - __half2float(h));
    v = w[idx];  h = __float2half(v); m[1536 + k] = h; m[3584 + k] = __float2half(v - __half2float(h));
}

// tiled transpose pack: fp32 W[L][K][512] -> fp16 out[L][512][K]
__global__ void pack_tiled(const float* __restrict__ W, __half* __restrict__ out, int K) {
    __shared__ float t[32][33];
    int k0 = blockIdx.x * 32, n0 = blockIdx.y * 32, l = blockIdx.z;
    const float* Wl = W + (size_t)l * K * 512;
    __half* ol = out + (size_t)l * 512 * K;
    int r = threadIdx.x >> 5, c = threadIdx.x & 31;
    #pragma unroll
    for (int i = 0; i < 4; i++)
        t[r + 8 * i][c] = Wl[(size_t)(k0 + r + 8 * i) * 512 + n0 + c];
    __syncthreads();
    #pragma unroll
    for (int i = 0; i < 4; i++) {
        int n = n0 + r + 8 * i;
        ol[(size_t)n * K + k0 + c] = __float2half(t[c][r + 8 * i]);
    }
}

// ---------------- GEMM ----------------
#define MODE_PLAIN 0
#define MODE_ADD   1
#define MODE_GATE  2
#define MODE_GELU  3

template<int MODE>
__device__ __forceinline__ void epi_store(int r, int c, float v0, float v1,
    const float* __restrict__ bias,
    __half* __restrict__ out, int ldo, int o_hi, int o_lo,
    const __half* __restrict__ aux, int ldx, int x_hi)
{
    v0 += bias[c];
    v1 += bias[c + 1];
    __half* orow = out + (size_t)r * ldo;
    if (MODE == MODE_ADD || MODE == MODE_GATE) {
        __half2 oh = *(const __half2*)(orow + o_hi + c);
        __half2 ol = *(const __half2*)(orow + o_lo + c);
        float old0 = __half2float(oh.x) + __half2float(ol.x);
        float old1 = __half2float(oh.y) + __half2float(ol.y);
        if (MODE == MODE_ADD) {
            v0 += old0; v1 += old1;
        } else {
            const __half* xrow = aux + (size_t)r * ldx;
            __half2 xh = *(const __half2*)(xrow + x_hi + c);
            float m0 = __half2float(xh.x);
            float m1 = __half2float(xh.y);
            float g0 = 1.f / (1.f + expf(-v0));
            float g1 = 1.f / (1.f + expf(-v1));
            v0 = old0 + (m0 - old0) * g0;
            v1 = old1 + (m1 - old1) * g1;
        }
    }
    if (MODE == MODE_GELU) {
        v0 = 0.5f * v0 * (1.f + erff(v0 * 0.70710678118654752f));
        v1 = 0.5f * v1 * (1.f + erff(v1 * 0.70710678118654752f));
    }
    __half h0 = __float2half(v0), h1 = __float2half(v1);
    __half2 hh; hh.x = h0; hh.y = h1;
    *(__half2*)(orow + o_hi + c) = hh;
    if (MODE == MODE_ADD || MODE == MODE_GATE) {
        __half2 ll;
        ll.x = __float2half(v0 - __half2float(h0));
        ll.y = __float2half(v1 - __half2float(h1));
        *(__half2*)(orow + o_lo + c) = ll;
    }
}

// M=128 x N=64 CTA tile. smem per stage: A 16K + B 8K = 24K; 3 stages = 72K
#define SAH(s) ((s) * 24576)
#define SBB(s) ((s) * 24576 + 16384)
#define GEMM_SMEM 73728

template<int MODE>
__global__ void __launch_bounds__(256, 2) gemm_lm(
    const __half* __restrict__ A, int lda, int a_hi, int a_zs, int K,
    const __half* __restrict__ Wp, int wp_zs,
    Bias4 b4,
    __half* __restrict__ out, int ldo, int o_hi, int o_lo, int out_zs,
    const __half* __restrict__ aux, int ldx, int x_hi)
{
    extern __shared__ __align__(1024) char dsm[];
    const uint32_t sb = (uint32_t)__cvta_generic_to_shared(dsm);
    const int tid = threadIdx.x, lane = tid & 31, warp = tid >> 5;
    const int wm = warp >> 1, wn = warp & 1;   // wm: 32-row strip, wn: 32-col strip
    const int bm = blockIdx.x, bn = blockIdx.y;
    const int z  = blockIdx.z;
    const int KT = K >> 6;

    a_hi += z * a_zs;
    Wp   += (size_t)z * wp_zs;
    out  += (size_t)z * out_zs;
    const float* bias = b4.p[z];

    float acc[2][4][4];
    #pragma unroll
    for (int i = 0; i < 2; i++)
        #pragma unroll
        for (int j = 0; j < 4; j++)
            #pragma unroll
            for (int q = 0; q < 4; q++) acc[i][j][q] = 0.f;

    const __half* Ab = A  + (size_t)bm * 128 * lda;
    const __half* Bb = Wp + (size_t)bn * 64 * K;

    auto load_stage = [&](int s, int kt) {
        const int k0 = kt << 6;
        #pragma unroll
        for (int i = 0; i < 4; i++) {          // A: 128 rows x 128B
            const int id = tid + 256 * i;
            const int row = id >> 3, c = id & 7;
            const uint32_t sw = (row << 7) | ((c ^ (row & 7)) << 4);
            cp16s(sb + SAH(s) + sw, Ab + (size_t)row * lda + a_hi + k0 + c * 8);
        }
        #pragma unroll
        for (int i = 0; i < 2; i++) {          // B: 64 rows x 128B
            const int id = tid + 256 * i;
            const int row = id >> 3, c = id & 7;
            const uint32_t sw = (row << 7) | ((c ^ (row & 7)) << 4);
            cp16s(sb + SBB(s) + sw, Bb + (size_t)row * K + k0 + c * 8);
        }
        asm volatile("cp.async.commit_group;");
    };

    load_stage(0, 0);
    load_stage(1, 1);

    const int lrow = lane & 15;
    const int lhi  = lane >> 4;
    const int lph  = lane & 7;
    const uint32_t aRow0 = (uint32_t)(wm * 32 + lrow) << 7;
    const uint32_t bRow0 = (uint32_t)(wn * 32 + lrow) << 7;

    int s = 0;
    for (int kt = 0; kt < KT; kt++) {
        if (kt + 2 < KT) {
            int s2 = s + 2; if (s2 >= 3) s2 -= 3;
            load_stage(s2, kt + 2);
            asm volatile("cp.async.wait_group 2;");
        } else if (kt + 1 < KT) {
            asm volatile("cp.async.wait_group 1;");
        } else {
            asm volatile("cp.async.wait_group 0;");
        }
        __syncthreads();
        const uint32_t aH = sb + SAH(s);
        const uint32_t bS = sb + SBB(s);

        #pragma unroll
        for (int kq = 0; kq < 4; kq++) {
            const uint32_t cb = (uint32_t)(((kq * 2 + lhi) ^ lph) << 4);
            uint32_t ah[2][4], b[2][4];
            #pragma unroll
            for (int mi = 0; mi < 2; mi++)
                ldmx4(aH + aRow0 + (uint32_t)(mi * 2048) + cb, ah[mi][0], ah[mi][1], ah[mi][2], ah[mi][3]);
            #pragma unroll
            for (int n2 = 0; n2 < 2; n2++)
                ldmx4(bS + bRow0 + (uint32_t)(n2 * 2048) + cb, b[n2][0], b[n2][1], b[n2][2], b[n2][3]);
            #pragma unroll
            for (int mi = 0; mi < 2; mi++)
                #pragma unroll
                for (int ni = 0; ni < 4; ni++)
                    MMA16(acc[mi][ni], ah[mi][0], ah[mi][1], ah[mi][2], ah[mi][3],
                          b[ni >> 1][ni & 1], b[ni >> 1][2 + (ni & 1)]);
        }
        __syncthreads();
        if (++s >= 3) s -= 3;
    }

    #pragma unroll
    for (int mi = 0; mi < 2; mi++) {
        #pragma unroll
        for (int ni = 0; ni < 4; ni++) {
            const int r0 = bm * 128 + wm * 32 + mi * 16 + (lane >> 2);
            const int c  = bn * 64 + wn * 32 + ni * 8 + (lane & 3) * 2;
            epi_store<MODE>(r0,     c, acc[mi][ni][0], acc[mi][ni][1], bias, out, ldo, o_hi, o_lo, aux, ldx, x_hi);
            epi_store<MODE>(r0 + 8, c, acc[mi][ni][2], acc[mi][ni][3], bias, out, ldo, o_hi, o_lo, aux, ldx, x_hi);
        }
    }
}

// ---------------- final tiny projections ----------------
__global__ void head2_kernel(
    const float* __restrict__ hsW2, const float* __restrict__ hsb2,
    const float* __restrict__ heW2, const float* __restrict__ heb2,
    const float* __restrict__ hfW2, const float* __restrict__ hfb2,
    const float* __restrict__ hwW2, const float* __restrict__ hwb2,
    float* __restrict__ out)
{
    int row  = blockIdx.x * 8 + (threadIdx.x >> 5);
    int lane = threadIdx.x & 31;
    const __half* h0 = g_HEADH + (size_t)row * 512;
    const __half* h1 = g_HEADH + (size_t)(BATCH + row) * 512;
    const __half* h2 = g_HEADH + (size_t)(2 * BATCH + row) * 512;
    const __half* h3 = g_HEADH + (size_t)(3 * BATCH + row) * 512;
    float acc[7] = {0.f, 0.f, 0.f, 0.f, 0.f, 0.f, 0.f};
    for (int k = lane; k < 512; k += 32) {
        float x0 = __half2float(h0[k]);
        float x1 = __half2float(h1[k]);
        float x2 = __half2float(h2[k]);
        float x3 = __half2float(h3[k]);
        acc[0] = fmaf(x0, hsW2[k * 3 + 0], acc[0]);
        acc[1] = fmaf(x0, hsW2[k * 3 + 1], acc[1]);
        acc[2] = fmaf(x0, hsW2[k * 3 + 2], acc[2]);
        acc[3] = fmaf(x1, heW2[k],         acc[3]);
        acc[4] = fmaf(x2, hfW2[k],         acc[4]);
        acc[5] = fmaf(x3, hwW2[k * 2 + 0], acc[5]);
        acc[6] = fmaf(x3, hwW2[k * 2 + 1], acc[6]);
    }
    #pragma unroll
    for (int j = 0; j < 7; j++)
        #pragma unroll
        for (int o = 16; o > 0; o >>= 1)
            acc[j] += __shfl_xor_sync(0xffffffffu, acc[j], o);
    if (lane == 0) {
        float* orow = out + (size_t)row * 7;
        orow[0] = acc[0] + hsb2[0];
        orow[1] = acc[1] + hsb2[1];
        orow[2] = acc[2] + hsb2[2];
        orow[3] = acc[3] + heb2[0];
        orow[4] = acc[4] + hfb2[0];
        orow[5] = acc[5] + hwb2[0];
        orow[6] = acc[6] + hwb2[1];
    }
}

// ---------------- host launch ----------------
extern "C" void kernel_launch(void* const* d_in, const int* in_sizes, int n_in,
                              void* d_out, int out_size) {
    (void)in_sizes; (void)n_in; (void)out_size;
    const float* sh    = (const float*)d_in[0];
    const float* el    = (const float*)d_in[1];
    const float* fa    = (const float*)d_in[2];
    const float* wr    = (const float*)d_in[3];
    const float* s2e_W = (const float*)d_in[4];
    const float* s2e_b = (const float*)d_in[5];
    const float* tf_W  = (const float*)d_in[6];
    const float* tf_b  = (const float*)d_in[7];
    const float* fw_W  = (const float*)d_in[8];
    const float* fw_b  = (const float*)d_in[9];
    const float* fg_W  = (const float*)d_in[10];
    const float* fg_b  = (const float*)d_in[11];
    const float* wg_W  = (const float*)d_in[12];
    const float* wg_b  = (const float*)d_in[13];
    const float* hsW1  = (const float*)d_in[14];
    const float* hsb1  = (const float*)d_in[15];
    const float* hsW2  = (const float*)d_in[16];
    const float* hsb2  = (const float*)d_in[17];
    const float* heW1  = (const float*)d_in[18];
    const float* heb1  = (const float*)d_in[19];
    const float* heW2  = (const float*)d_in[20];
    const float* heb2  = (const float*)d_in[21];
    const float* hfW1  = (const float*)d_in[22];
    const float* hfb1  = (const float*)d_in[23];
    const float* hfW2  = (const float*)d_in[24];
    const float* hfb2  = (const float*)d_in[25];
    const float* hwW1  = (const float*)d_in[26];
    const float* hwb1  = (const float*)d_in[27];
    const float* hwW2  = (const float*)d_in[28];
    const float* hwb2  = (const float*)d_in[29];

    __half *WP, *MEGA, *SCRATCH, *HEADH;
    cudaGetSymbolAddress((void**)&WP,      g_WP);
    cudaGetSymbolAddress((void**)&MEGA,    g_MEGA);
    cudaGetSymbolAddress((void**)&SCRATCH, g_SCRATCH);
    cudaGetSymbolAddress((void**)&HEADH,   g_HEADH);

    cudaFuncSetAttribute(gemm_lm<MODE_PLAIN>, cudaFuncAttributeMaxDynamicSharedMemorySize, GEMM_SMEM);
    cudaFuncSetAttribute(gemm_lm<MODE_ADD>,   cudaFuncAttributeMaxDynamicSharedMemorySize, GEMM_SMEM);
    cudaFuncSetAttribute(gemm_lm<MODE_GATE>,  cudaFuncAttributeMaxDynamicSharedMemorySize, GEMM_SMEM);
    cudaFuncSetAttribute(gemm_lm<MODE_GELU>,  cudaFuncAttributeMaxDynamicSharedMemorySize, GEMM_SMEM);

    dim3 grid(BATCH / 128, 8, 1);
    auto B1 = [](const float* p) { Bias4 b; b.p[0] = b.p[1] = b.p[2] = b.p[3] = p; return b; };

    split_inputs_kernel<<<(BATCH * HDIM + 255) / 256, 256>>>(sh, el, fa, wr);

    pack_tiled<<<dim3(16, 16, 5), 256>>>(s2e_W, WP + S2E_OFF, 512);
    pack_tiled<<<dim3(32, 16, 5), 256>>>(tf_W,  WP + TF_OFF,  1024);
    pack_tiled<<<dim3(16, 16, 5), 256>>>(fg_W,  WP + FG_OFF,  512);
    pack_tiled<<<dim3(32, 16, 5), 256>>>(fw_W,  WP + FW_OFF,  1024);
    pack_tiled<<<dim3(16, 16, 5), 256>>>(wg_W,  WP + WG_OFF,  512);
    pack_tiled<<<dim3(16, 16, 1), 256>>>(hsW1, WP + H1_OFF + 0 * S2E_SZ, 512);
    pack_tiled<<<dim3(16, 16, 1), 256>>>(heW1, WP + H1_OFF + 1 * S2E_SZ, 512);
    pack_tiled<<<dim3(16, 16, 1), 256>>>(hfW1, WP + H1_OFF + 2 * S2E_SZ, 512);
    pack_tiled<<<dim3(16, 16, 1), 256>>>(hwW1, WP + H1_OFF + 3 * S2E_SZ, 512);

    for (int i = 0; i < NL; i++) {
        // e = e + sh @ W + b
        gemm_lm<MODE_ADD><<<grid, 256, GEMM_SMEM>>>(
            MEGA, 4096, 0, 0, 512,
            WP + S2E_OFF + (size_t)i * S2E_SZ, 0, B1(s2e_b + i * 512),
            MEGA, 4096, 512, 2560, 0, nullptr, 0, 0);
        // fm = [sh_hi, e_hi] @ W + b -> SCRATCH (hi only)
        gemm_lm<MODE_PLAIN><<<grid, 256, GEMM_SMEM>>>(
            MEGA, 4096, 0, 0, 1024,
            WP + TF_OFF + (size_t)i * TF_SZ, 0, B1(tf_b + i * 512),
            SCRATCH, 512, 0, 0, 0, nullptr, 0, 0);
        // g = sigmoid(fm @ W + b); f = f*(1-g) + fm*g
        gemm_lm<MODE_GATE><<<grid, 256, GEMM_SMEM>>>(
            SCRATCH, 512, 0, 0, 512,
            WP + FG_OFF + (size_t)i * S2E_SZ, 0, B1(fg_b + i * 512),
            MEGA, 4096, 1024, 3072, 0, SCRATCH, 512, 0);
        // wm = [e_hi, f_hi] @ W + b
        gemm_lm<MODE_PLAIN><<<grid, 256, GEMM_SMEM>>>(
            MEGA, 4096, 512, 0, 1024,
            WP + FW_OFF + (size_t)i * TF_SZ, 0, B1(fw_b + i * 512),
            SCRATCH, 512, 0, 0, 0, nullptr, 0, 0);
        // g = sigmoid(wm @ W + b); w = w*(1-g) + wm*g
        gemm_lm<MODE_GATE><<<grid, 256, GEMM_SMEM>>>(
            SCRATCH, 512, 0, 0, 512,
            WP + WG_OFF + (size_t)i * S2E_SZ, 0, B1(wg_b + i * 512),
            MEGA, 4096, 1536, 3584, 0, SCRATCH, 512, 0);
    }

    // all 4 heads in one launch: z selects head
    {
        Bias4 hb; hb.p[0] = hsb1; hb.p[1] = heb1; hb.p[2] = hfb1; hb.p[3] = hwb1;
        dim3 grid4(BATCH / 128, 8, 4);
        gemm_lm<MODE_GELU><<<grid4, 256, GEMM_SMEM>>>(
            MEGA, 4096, 0, 512, 512,
            WP + H1_OFF, S2E_SZ, hb,
            HEADH, 512, 0, 0, BATCH * 512, nullptr, 0, 0);
    }

    head2_kernel<<<BATCH / 8, 256>>>(hsW2, hsb2, heW2, heb2, hfW2, hfb2,
                                     hwW2, hwb2, (float*)d_out);
}

// round 11
// speedup vs baseline: 1.5457x; 1.5457x over previous
#include <cuda_runtime.h>
#include <cuda_fp16.h>
#include <cstdint>
#include <cmath>

#define BATCH 32768
#define HDIM  512
#define NL    5

// ---------------- static device buffers ----------------
#define S2E_SZ (512*512)
#define TF_SZ  (512*1024)
#define S2E_OFF 0
#define TF_OFF  (S2E_OFF + 5*S2E_SZ)
#define FG_OFF  (TF_OFF  + 5*TF_SZ)
#define FW_OFF  (FG_OFF  + 5*S2E_SZ)
#define WG_OFF  (FW_OFF  + 5*TF_SZ)
#define H1_OFF  (WG_OFF  + 5*S2E_SZ)
#define WP_TOTAL (H1_OFF + 4*S2E_SZ)

__device__ __half g_WP[WP_TOTAL];
// per row: [sh_h(512) e_h f_h w_h | (unused) e_l f_l w_l] -> 4096 halves
__device__ __half g_MEGA[(size_t)BATCH * 4096];
__device__ __half g_SCRATCH[(size_t)BATCH * 512];   // fm/wm hi only
__device__ __half g_HEADH[(size_t)4 * BATCH * 512]; // head hiddens hi only

struct Bias4 { const float* p[4]; };
struct PackJob { const float* src[10]; unsigned dst[10]; };

// ---------------- helpers ----------------
__device__ __forceinline__ void cp16s(uint32_t sa, const void* g) {
    asm volatile("cp.async.cg.shared.global [%0], [%1], 16;" :: "r"(sa), "l"(g));
}
__device__ __forceinline__ void ldmx4(uint32_t addr, uint32_t& r0, uint32_t& r1, uint32_t& r2, uint32_t& r3) {
    asm volatile("ldmatrix.sync.aligned.m8n8.x4.shared.b16 {%0,%1,%2,%3}, [%4];"
        : "=r"(r0), "=r"(r1), "=r"(r2), "=r"(r3) : "r"(addr));
}
#define MMA16(acc, a0,a1,a2,a3, b0,b1) \
    asm volatile("mma.sync.aligned.m16n8k16.row.col.f32.f16.f16.f32 " \
        "{%0,%1,%2,%3},{%4,%5,%6,%7},{%8,%9},{%0,%1,%2,%3};" \
        : "+f"((acc)[0]), "+f"((acc)[1]), "+f"((acc)[2]), "+f"((acc)[3]) \
        : "r"(a0), "r"(a1), "r"(a2), "r"(a3), "r"(b0), "r"(b1))

// ---------------- setup kernels ----------------
__global__ void split_inputs_kernel(const float* __restrict__ sh, const float* __restrict__ e,
                                    const float* __restrict__ f,  const float* __restrict__ w) {
    int idx = blockIdx.x * 256 + threadIdx.x;
    if (idx >= BATCH * HDIM) return;
    int row = idx >> 9, k = idx & 511;
    __half* m = g_MEGA + (size_t)row * 4096;
    float v; __half h;
    v = sh[idx]; m[k] = __float2half(v);   // sh_lo never read -> not stored
    v = e[idx];  h = __float2half(v); m[512 + k]  = h; m[2560 + k] = __float2half(v - __half2float(h));
    v = f[idx];  h = __float2half(v); m[1024 + k] = h; m[3072 + k] = __float2half(v - __half2float(h));
    v = w[idx];  h = __float2half(v); m[1536 + k] = h; m[3584 + k] = __float2half(v - __half2float(h));
}

// multi-matrix tiled transpose pack: fp32 W[K][512] -> fp16 g_WP[dst + n*K + k]
__global__ void pack_multi(PackJob job, int K) {
    __shared__ float t[32][33];
    int k0 = blockIdx.x * 32, n0 = blockIdx.y * 32, j = blockIdx.z;
    const float* Wl = job.src[j];
    __half* ol = g_WP + job.dst[j];
    int r = threadIdx.x >> 5, c = threadIdx.x & 31;
    #pragma unroll
    for (int i = 0; i < 4; i++)
        t[r + 8 * i][c] = Wl[(size_t)(k0 + r + 8 * i) * 512 + n0 + c];
    __syncthreads();
    #pragma unroll
    for (int i = 0; i < 4; i++) {
        int n = n0 + r + 8 * i;
        ol[(size_t)n * K + k0 + c] = __float2half(t[c][r + 8 * i]);
    }
}

// ---------------- GEMM ----------------
#define MODE_PLAIN 0
#define MODE_ADD   1
#define MODE_GATE  2
#define MODE_GELU  3

template<int MODE>
__device__ __forceinline__ void epi_store(int r, int c, float v0, float v1,
    const float* __restrict__ bias,
    __half* __restrict__ out, int ldo, int o_hi, int o_lo,
    const __half* __restrict__ aux, int ldx, int x_hi)
{
    v0 += bias[c];
    v1 += bias[c + 1];
    __half* orow = out + (size_t)r * ldo;
    if (MODE == MODE_ADD || MODE == MODE_GATE) {
        __half2 oh = *(const __half2*)(orow + o_hi + c);
        __half2 ol = *(const __half2*)(orow + o_lo + c);
        float old0 = __half2float(oh.x) + __half2float(ol.x);
        float old1 = __half2float(oh.y) + __half2float(ol.y);
        if (MODE == MODE_ADD) {
            v0 += old0; v1 += old1;
        } else {
            const __half* xrow = aux + (size_t)r * ldx;
            __half2 xh = *(const __half2*)(xrow + x_hi + c);
            float m0 = __half2float(xh.x);
            float m1 = __half2float(xh.y);
            float g0 = 1.f / (1.f + expf(-v0));
            float g1 = 1.f / (1.f + expf(-v1));
            v0 = old0 + (m0 - old0) * g0;
            v1 = old1 + (m1 - old1) * g1;
        }
    }
    if (MODE == MODE_GELU) {
        v0 = 0.5f * v0 * (1.f + erff(v0 * 0.70710678118654752f));
        v1 = 0.5f * v1 * (1.f + erff(v1 * 0.70710678118654752f));
    }
    __half h0 = __float2half(v0), h1 = __float2half(v1);
    __half2 hh; hh.x = h0; hh.y = h1;
    *(__half2*)(orow + o_hi + c) = hh;
    if (MODE == MODE_ADD || MODE == MODE_GATE) {
        __half2 ll;
        ll.x = __float2half(v0 - __half2float(h0));
        ll.y = __float2half(v1 - __half2float(h1));
        *(__half2*)(orow + o_lo + c) = ll;
    }
}

// M=128 x N=128 CTA tile. smem per stage: A 16K + B 16K = 32K; 3 stages = 96K
#define SAH(s) ((s) * 32768)
#define SBB(s) ((s) * 32768 + 16384)
#define GEMM_SMEM 98304

template<int MODE>
__global__ void __launch_bounds__(256, 2) gemm_lm(
    const __half* __restrict__ A, int lda, int a_hi, int a_zs, int K,
    const __half* __restrict__ Wp, int wp_zs,
    Bias4 b4,
    __half* __restrict__ out, int ldo, int o_hi, int o_lo, int out_zs,
    const __half* __restrict__ aux, int ldx, int x_hi)
{
    extern __shared__ __align__(1024) char dsm[];
    const uint32_t sb = (uint32_t)__cvta_generic_to_shared(dsm);
    const int tid = threadIdx.x, lane = tid & 31, warp = tid >> 5;
    const int wm = warp >> 1, wn = warp & 1;
    const int bm = blockIdx.x, bn = blockIdx.y;
    const int z  = blockIdx.z;
    const int KT = K >> 6;

    a_hi += z * a_zs;
    Wp   += (size_t)z * wp_zs;
    out  += (size_t)z * out_zs;
    const float* bias = b4.p[z];

    float acc[2][8][4];
    #pragma unroll
    for (int i = 0; i < 2; i++)
        #pragma unroll
        for (int j = 0; j < 8; j++)
            #pragma unroll
            for (int q = 0; q < 4; q++) acc[i][j][q] = 0.f;

    const __half* Ab = A  + (size_t)bm * 128 * lda;
    const __half* Bb = Wp + (size_t)bn * 128 * K;

    auto load_stage = [&](int s, int kt) {
        const int k0 = kt << 6;
        #pragma unroll
        for (int i = 0; i < 4; i++) {
            const int id = tid + 256 * i;
            const int row = id >> 3, c = id & 7;
            const uint32_t sw = (row << 7) | ((c ^ (row & 7)) << 4);
            cp16s(sb + SAH(s) + sw, Ab + (size_t)row * lda + a_hi + k0 + c * 8);
            cp16s(sb + SBB(s) + sw, Bb + (size_t)row * K   + k0   + c * 8);
        }
        asm volatile("cp.async.commit_group;");
    };

    load_stage(0, 0);
    load_stage(1, 1);

    const int lrow = lane & 15;
    const int lhi  = lane >> 4;
    const int lph  = lane & 7;
    const uint32_t aRow0 = (uint32_t)(wm * 32 + lrow) << 7;
    const uint32_t bRow0 = (uint32_t)(wn * 64 + lrow) << 7;

    int s = 0;
    for (int kt = 0; kt < KT; kt++) {
        // wait for stage kt's data, then ONE barrier per iteration.
        if (kt + 1 < KT) asm volatile("cp.async.wait_group 1;");
        else             asm volatile("cp.async.wait_group 0;");
        __syncthreads();
        // after the barrier every warp finished reading stage (s+2)%3 in
        // iteration kt-1, so it is safe to overwrite it now.
        if (kt + 2 < KT) {
            int s2 = s + 2; if (s2 >= 3) s2 -= 3;
            load_stage(s2, kt + 2);
        }
        const uint32_t aH = sb + SAH(s);
        const uint32_t bS = sb + SBB(s);

        #pragma unroll
        for (int kq = 0; kq < 4; kq++) {
            const uint32_t cb = (uint32_t)(((kq * 2 + lhi) ^ lph) << 4);
            uint32_t ah[2][4], b[4][4];
            #pragma unroll
            for (int mi = 0; mi < 2; mi++)
                ldmx4(aH + aRow0 + (uint32_t)(mi * 2048) + cb, ah[mi][0], ah[mi][1], ah[mi][2], ah[mi][3]);
            #pragma unroll
            for (int n2 = 0; n2 < 4; n2++)
                ldmx4(bS + bRow0 + (uint32_t)(n2 * 2048) + cb, b[n2][0], b[n2][1], b[n2][2], b[n2][3]);
            #pragma unroll
            for (int mi = 0; mi < 2; mi++)
                #pragma unroll
                for (int ni = 0; ni < 8; ni++)
                    MMA16(acc[mi][ni], ah[mi][0], ah[mi][1], ah[mi][2], ah[mi][3],
                          b[ni >> 1][ni & 1], b[ni >> 1][2 + (ni & 1)]);
        }
        if (++s >= 3) s -= 3;
    }

    #pragma unroll
    for (int mi = 0; mi < 2; mi++) {
        #pragma unroll
        for (int ni = 0; ni < 8; ni++) {
            const int r0 = bm * 128 + wm * 32 + mi * 16 + (lane >> 2);
            const int c  = bn * 128 + wn * 64 + ni * 8 + (lane & 3) * 2;
            epi_store<MODE>(r0,     c, acc[mi][ni][0], acc[mi][ni][1], bias, out, ldo, o_hi, o_lo, aux, ldx, x_hi);
            epi_store<MODE>(r0 + 8, c, acc[mi][ni][2], acc[mi][ni][3], bias, out, ldo, o_hi, o_lo, aux, ldx, x_hi);
        }
    }
}

// ---------------- final tiny projections ----------------
__global__ void head2_kernel(
    const float* __restrict__ hsW2, const float* __restrict__ hsb2,
    const float* __restrict__ heW2, const float* __restrict__ heb2,
    const float* __restrict__ hfW2, const float* __restrict__ hfb2,
    const float* __restrict__ hwW2, const float* __restrict__ hwb2,
    float* __restrict__ out)
{
    int row  = blockIdx.x * 8 + (threadIdx.x >> 5);
    int lane = threadIdx.x & 31;
    const __half* h0 = g_HEADH + (size_t)row * 512;
    const __half* h1 = g_HEADH + (size_t)(BATCH + row) * 512;
    const __half* h2 = g_HEADH + (size_t)(2 * BATCH + row) * 512;
    const __half* h3 = g_HEADH + (size_t)(3 * BATCH + row) * 512;
    float acc[7] = {0.f, 0.f, 0.f, 0.f, 0.f, 0.f, 0.f};
    for (int k = lane; k < 512; k += 32) {
        float x0 = __half2float(h0[k]);
        float x1 = __half2float(h1[k]);
        float x2 = __half2float(h2[k]);
        float x3 = __half2float(h3[k]);
        acc[0] = fmaf(x0, hsW2[k * 3 + 0], acc[0]);
        acc[1] = fmaf(x0, hsW2[k * 3 + 1], acc[1]);
        acc[2] = fmaf(x0, hsW2[k * 3 + 2], acc[2]);
        acc[3] = fmaf(x1, heW2[k],         acc[3]);
        acc[4] = fmaf(x2, hfW2[k],         acc[4]);
        acc[5] = fmaf(x3, hwW2[k * 2 + 0], acc[5]);
        acc[6] = fmaf(x3, hwW2[k * 2 + 1], acc[6]);
    }
    #pragma unroll
    for (int j = 0; j < 7; j++)
        #pragma unroll
        for (int o = 16; o > 0; o >>= 1)
            acc[j] += __shfl_xor_sync(0xffffffffu, acc[j], o);
    if (lane == 0) {
        float* orow = out + (size_t)row * 7;
        orow[0] = acc[0] + hsb2[0];
        orow[1] = acc[1] + hsb2[1];
        orow[2] = acc[2] + hsb2[2];
        orow[3] = acc[3] + heb2[0];
        orow[4] = acc[4] + hfb2[0];
        orow[5] = acc[5] + hwb2[0];
        orow[6] = acc[6] + hwb2[1];
    }
}

// ---------------- host launch ----------------
extern "C" void kernel_launch(void* const* d_in, const int* in_sizes, int n_in,
                              void* d_out, int out_size) {
    (void)in_sizes; (void)n_in; (void)out_size;
    const float* sh    = (const float*)d_in[0];
    const float* el    = (const float*)d_in[1];
    const float* fa    = (const float*)d_in[2];
    const float* wr    = (const float*)d_in[3];
    const float* s2e_W = (const float*)d_in[4];
    const float* s2e_b = (const float*)d_in[5];
    const float* tf_W  = (const float*)d_in[6];
    const float* tf_b  = (const float*)d_in[7];
    const float* fw_W  = (const float*)d_in[8];
    const float* fw_b  = (const float*)d_in[9];
    const float* fg_W  = (const float*)d_in[10];
    const float* fg_b  = (const float*)d_in[11];
    const float* wg_W  = (const float*)d_in[12];
    const float* wg_b  = (const float*)d_in[13];
    const float* hsW1  = (const float*)d_in[14];
    const float* hsb1  = (const float*)d_in[15];
    const float* hsW2  = (const float*)d_in[16];
    const float* hsb2  = (const float*)d_in[17];
    const float* heW1  = (const float*)d_in[18];
    const float* heb1  = (const float*)d_in[19];
    const float* heW2  = (const float*)d_in[20];
    const float* heb2  = (const float*)d_in[21];
    const float* hfW1  = (const float*)d_in[22];
    const float* hfb1  = (const float*)d_in[23];
    const float* hfW2  = (const float*)d_in[24];
    const float* hfb2  = (const float*)d_in[25];
    const float* hwW1  = (const float*)d_in[26];
    const float* hwb1  = (const float*)d_in[27];
    const float* hwW2  = (const float*)d_in[28];
    const float* hwb2  = (const float*)d_in[29];

    __half *WP, *MEGA, *SCRATCH, *HEADH;
    cudaGetSymbolAddress((void**)&WP,      g_WP);
    cudaGetSymbolAddress((void**)&MEGA,    g_MEGA);
    cudaGetSymbolAddress((void**)&SCRATCH, g_SCRATCH);
    cudaGetSymbolAddress((void**)&HEADH,   g_HEADH);

    cudaFuncSetAttribute(gemm_lm<MODE_PLAIN>, cudaFuncAttributeMaxDynamicSharedMemorySize, GEMM_SMEM);
    cudaFuncSetAttribute(gemm_lm<MODE_ADD>,   cudaFuncAttributeMaxDynamicSharedMemorySize, GEMM_SMEM);
    cudaFuncSetAttribute(gemm_lm<MODE_GATE>,  cudaFuncAttributeMaxDynamicSharedMemorySize, GEMM_SMEM);
    cudaFuncSetAttribute(gemm_lm<MODE_GELU>,  cudaFuncAttributeMaxDynamicSharedMemorySize, GEMM_SMEM);

    dim3 grid(BATCH / 128, 4, 1);
    auto B1 = [](const float* p) { Bias4 b; b.p[0] = b.p[1] = b.p[2] = b.p[3] = p; return b; };

    // launch 0
    split_inputs_kernel<<<(BATCH * HDIM + 255) / 256, 256>>>(sh, el, fa, wr);

    // launch 1: s2e (5) + fg (5), K=512
    {
        PackJob j{};
        for (int i = 0; i < 5; i++) {
            j.src[i]     = s2e_W + (size_t)i * 512 * 512; j.dst[i]     = S2E_OFF + i * S2E_SZ;
            j.src[5 + i] = fg_W  + (size_t)i * 512 * 512; j.dst[5 + i] = FG_OFF  + i * S2E_SZ;
        }
        pack_multi<<<dim3(16, 16, 10), 256>>>(j, 512);
    }
    // launch 2: wg (5) + heads (4), K=512
    {
        PackJob j{};
        for (int i = 0; i < 5; i++) { j.src[i] = wg_W + (size_t)i * 512 * 512; j.dst[i] = WG_OFF + i * S2E_SZ; }
        j.src[5] = hsW1; j.dst[5] = H1_OFF + 0 * S2E_SZ;
        j.src[6] = heW1; j.dst[6] = H1_OFF + 1 * S2E_SZ;
        j.src[7] = hfW1; j.dst[7] = H1_OFF + 2 * S2E_SZ;
        j.src[8] = hwW1; j.dst[8] = H1_OFF + 3 * S2E_SZ;
        pack_multi<<<dim3(16, 16, 9), 256>>>(j, 512);
    }
    // launch 3: tf (5), K=1024
    {
        PackJob j{};
        for (int i = 0; i < 5; i++) { j.src[i] = tf_W + (size_t)i * 1024 * 512; j.dst[i] = TF_OFF + i * TF_SZ; }
        pack_multi<<<dim3(32, 16, 5), 256>>>(j, 1024);
    }
    // launch 4: fw (5), K=1024
    {
        PackJob j{};
        for (int i = 0; i < 5; i++) { j.src[i] = fw_W + (size_t)i * 1024 * 512; j.dst[i] = FW_OFF + i * TF_SZ; }
        pack_multi<<<dim3(32, 16, 5), 256>>>(j, 1024);
    }

    // launch 5 onward: GEMMs (ncu -s 5 profiles the first one)
    for (int i = 0; i < NL; i++) {
        // e = e + sh @ W + b
        gemm_lm<MODE_ADD><<<grid, 256, GEMM_SMEM>>>(
            MEGA, 4096, 0, 0, 512,
            WP + S2E_OFF + (size_t)i * S2E_SZ, 0, B1(s2e_b + i * 512),
            MEGA, 4096, 512, 2560, 0, nullptr, 0, 0);
        // fm = [sh_hi, e_hi] @ W + b -> SCRATCH (hi only)
        gemm_lm<MODE_PLAIN><<<grid, 256, GEMM_SMEM>>>(
            MEGA, 4096, 0, 0, 1024,
            WP + TF_OFF + (size_t)i * TF_SZ, 0, B1(tf_b + i * 512),
            SCRATCH, 512, 0, 0, 0, nullptr, 0, 0);
        // g = sigmoid(fm @ W + b); f = f*(1-g) + fm*g
        gemm_lm<MODE_GATE><<<grid, 256, GEMM_SMEM>>>(
            SCRATCH, 512, 0, 0, 512,
            WP + FG_OFF + (size_t)i * S2E_SZ, 0, B1(fg_b + i * 512),
            MEGA, 4096, 1024, 3072, 0, SCRATCH, 512, 0);
        // wm = [e_hi, f_hi] @ W + b
        gemm_lm<MODE_PLAIN><<<grid, 256, GEMM_SMEM>>>(
            MEGA, 4096, 512, 0, 1024,
            WP + FW_OFF + (size_t)i * TF_SZ, 0, B1(fw_b + i * 512),
            SCRATCH, 512, 0, 0, 0, nullptr, 0, 0);
        // g = sigmoid(wm @ W + b); w = w*(1-g) + wm*g
        gemm_lm<MODE_GATE><<<grid, 256, GEMM_SMEM>>>(
            SCRATCH, 512, 0, 0, 512,
            WP + WG_OFF + (size_t)i * S2E_SZ, 0, B1(wg_b + i * 512),
            MEGA, 4096, 1536, 3584, 0, SCRATCH, 512, 0);
    }

    // all 4 heads in one launch: z selects head
    {
        Bias4 hb; hb.p[0] = hsb1; hb.p[1] = heb1; hb.p[2] = hfb1; hb.p[3] = hwb1;
        dim3 grid4(BATCH / 128, 4, 4);
        gemm_lm<MODE_GELU><<<grid4, 256, GEMM_SMEM>>>(
            MEGA, 4096, 0, 512, 512,
            WP + H1_OFF, S2E_SZ, hb,
            HEADH, 512, 0, 0, BATCH * 512, nullptr, 0, 0);
    }

    head2_kernel<<<BATCH / 8, 256>>>(hsW2, hsb2, heW2, heb2, hfW2, hfb2,
                                     hwW2, hwb2, (float*)d_out);
}

// round 12
// speedup vs baseline: 1.7217x; 1.1139x over previous
#include <cuda_runtime.h>
#include <cuda_fp16.h>
#include <cstdint>
#include <cmath>

#define BATCH 32768
#define NE ((size_t)BATCH * 512)

// ---------------- packed weights ----------------
#define S2E_SZ (512*512)
#define TF_SZ  (512*1024)
#define S2E_OFF 0
#define TF_OFF  (S2E_OFF + 5*S2E_SZ)
#define FG_OFF  (TF_OFF  + 5*TF_SZ)
#define FW_OFF  (FG_OFF  + 5*S2E_SZ)
#define WG_OFF  (FW_OFF  + 5*TF_SZ)
#define H1_OFF  (WG_OFF  + 5*S2E_SZ)
#define WP_TOTAL (H1_OFF + 4*S2E_SZ)

__device__ __half g_WP[WP_TOTAL];
__device__ __half g_SH[NE];
__device__ __half g_EINH[NE]; __device__ __half g_EINL[NE];
__device__ __half g_FINH[NE]; __device__ __half g_FINL[NE];
__device__ __half g_WINH[NE]; __device__ __half g_WINL[NE];
__device__ __half g_P[10 * NE];   // hi: z*NE, lo: (5+z)*NE
__device__ __half g_E[5 * NE];
__device__ __half g_FM[5 * NE];
__device__ __half g_GF[5 * NE];
__device__ __half g_F[5 * NE];
__device__ __half g_WM[5 * NE];
__device__ __half g_GW[5 * NE];
__device__ __half g_W4[NE];
__device__ __half g_HEADH[4 * NE];

struct HP5 { const __half* p[5]; };
struct FP5 { const float* p[5]; };
struct PackJob { const float* src[10]; unsigned dst[10]; };

// ---------------- helpers ----------------
__device__ __forceinline__ void cp16s(uint32_t sa, const void* g) {
    asm volatile("cp.async.cg.shared.global [%0], [%1], 16;" :: "r"(sa), "l"(g));
}
__device__ __forceinline__ void ldmx4(uint32_t addr, uint32_t& r0, uint32_t& r1, uint32_t& r2, uint32_t& r3) {
    asm volatile("ldmatrix.sync.aligned.m8n8.x4.shared.b16 {%0,%1,%2,%3}, [%4];"
        : "=r"(r0), "=r"(r1), "=r"(r2), "=r"(r3) : "r"(addr));
}
#define MMA16(acc, a0,a1,a2,a3, b0,b1) \
    asm volatile("mma.sync.aligned.m16n8k16.row.col.f32.f16.f16.f32 " \
        "{%0,%1,%2,%3},{%4,%5,%6,%7},{%8,%9},{%0,%1,%2,%3};" \
        : "+f"((acc)[0]), "+f"((acc)[1]), "+f"((acc)[2]), "+f"((acc)[3]) \
        : "r"(a0), "r"(a1), "r"(a2), "r"(a3), "r"(b0), "r"(b1))

// ---------------- setup kernels ----------------
__global__ void split_inputs_kernel(const float* __restrict__ sh, const float* __restrict__ e,
                                    const float* __restrict__ f,  const float* __restrict__ w) {
    size_t i = (size_t)blockIdx.x * 256 + threadIdx.x;
    if (i >= NE) return;
    float v; __half h;
    g_SH[i] = __float2half(sh[i]);
    v = e[i]; h = __float2half(v); g_EINH[i] = h; g_EINL[i] = __float2half(v - __half2float(h));
    v = f[i]; h = __float2half(v); g_FINH[i] = h; g_FINL[i] = __float2half(v - __half2float(h));
    v = w[i]; h = __float2half(v); g_WINH[i] = h; g_WINL[i] = __float2half(v - __half2float(h));
}

// tiled transpose pack: fp32 W[K][512] -> fp16 g_WP[dst + n*K + (k^xmask)]
__global__ void pack_multi(PackJob job, int K, int xmask) {
    __shared__ float t[32][33];
    int k0 = blockIdx.x * 32, n0 = blockIdx.y * 32, j = blockIdx.z;
    const float* Wl = job.src[j];
    __half* ol = g_WP + job.dst[j];
    int r = threadIdx.x >> 5, c = threadIdx.x & 31;
    #pragma unroll
    for (int i = 0; i < 4; i++)
        t[r + 8 * i][c] = Wl[(size_t)(k0 + r + 8 * i) * 512 + n0 + c];
    __syncthreads();
    #pragma unroll
    for (int i = 0; i < 4; i++) {
        int n = n0 + r + 8 * i;
        ol[(size_t)n * K + ((k0 + c) ^ xmask)] = __float2half(t[c][r + 8 * i]);
    }
}

// ---------------- elementwise chains ----------------
__global__ void ecumsum_kernel() {
    size_t i = (size_t)blockIdx.x * 256 + threadIdx.x;
    if (i >= NE) return;
    float e = __half2float(g_EINH[i]) + __half2float(g_EINL[i]);
    #pragma unroll
    for (int z = 0; z < 5; z++) {
        e += __half2float(g_P[(size_t)z * NE + i]) + __half2float(g_P[(size_t)(5 + z) * NE + i]);
        g_E[(size_t)z * NE + i] = __float2half(e);
    }
}
__global__ void fchain_kernel() {
    size_t i = (size_t)blockIdx.x * 256 + threadIdx.x;
    if (i >= NE) return;
    float f = __half2float(g_FINH[i]) + __half2float(g_FINL[i]);
    #pragma unroll
    for (int z = 0; z < 5; z++) {
        float g  = __half2float(g_GF[(size_t)z * NE + i]);
        float fm = __half2float(g_FM[(size_t)z * NE + i]);
        f = f + (fm - f) * g;
        g_F[(size_t)z * NE + i] = __float2half(f);
    }
}
__global__ void wchain_kernel() {
    size_t i = (size_t)blockIdx.x * 256 + threadIdx.x;
    if (i >= NE) return;
    float w = __half2float(g_WINH[i]) + __half2float(g_WINL[i]);
    #pragma unroll
    for (int z = 0; z < 5; z++) {
        float g  = __half2float(g_GW[(size_t)z * NE + i]);
        float wm = __half2float(g_WM[(size_t)z * NE + i]);
        w = w + (wm - w) * g;
    }
    g_W4[i] = __float2half(w);
}

// ---------------- GEMM ----------------
#define MODE_PLAIN 0
#define MODE_HILO  1
#define MODE_SIG   2
#define MODE_GELU  3

template<int MODE>
__device__ __forceinline__ void epi_store(__half* orow, int c, float v0, float v1,
                                          const float* __restrict__ bias, int lo_off)
{
    v0 += bias[c];
    v1 += bias[c + 1];
    if (MODE == MODE_SIG) {
        v0 = 1.f / (1.f + expf(-v0));
        v1 = 1.f / (1.f + expf(-v1));
    }
    if (MODE == MODE_GELU) {
        v0 = 0.5f * v0 * (1.f + erff(v0 * 0.70710678118654752f));
        v1 = 0.5f * v1 * (1.f + erff(v1 * 0.70710678118654752f));
    }
    __half h0 = __float2half(v0), h1 = __float2half(v1);
    __half2 hh; hh.x = h0; hh.y = h1;
    *(__half2*)(orow + c) = hh;
    if (MODE == MODE_HILO) {
        __half2 ll;
        ll.x = __float2half(v0 - __half2float(h0));
        ll.y = __float2half(v1 - __half2float(h1));
        *(__half2*)(orow + lo_off + c) = ll;
    }
}

// M=128 x N=128 CTA tile. smem per stage: A 16K + B 16K = 32K; 3 stages = 96K
#define SAH(s) ((s) * 32768)
#define SBB(s) ((s) * 32768 + 16384)
#define GEMM_SMEM 98304

template<int MODE>
__global__ void __launch_bounds__(256, 2) gemm_lm(
    HP5 a1, HP5 a2, const __half* __restrict__ Wp, unsigned wp_zs, int K,
    FP5 bias, __half* __restrict__ out, unsigned out_zs, int lo_off)
{
    extern __shared__ __align__(1024) char dsm[];
    const uint32_t sb = (uint32_t)__cvta_generic_to_shared(dsm);
    const int tid = threadIdx.x, lane = tid & 31, warp = tid >> 5;
    const int wm = warp >> 1, wn = warp & 1;
    const int bm = blockIdx.x, bn = blockIdx.y;
    const int z  = blockIdx.z;
    const int KT = K >> 6;

    const __half* a1p = a1.p[z] + (size_t)bm * 128 * 512;
    const __half* a2p = a2.p[z] + (size_t)bm * 128 * 512;
    const __half* Bb  = Wp + (size_t)z * wp_zs + (size_t)bn * 128 * K;
    const float*  bz  = bias.p[z];
    out += (size_t)z * out_zs;

    float acc[2][8][4];
    #pragma unroll
    for (int i = 0; i < 2; i++)
        #pragma unroll
        for (int j = 0; j < 8; j++)
            #pragma unroll
            for (int q = 0; q < 4; q++) acc[i][j][q] = 0.f;

    auto load_stage = [&](int s, int kt) {
        const int k0 = kt << 6;
        const __half* base = (k0 < 512) ? (a1p + k0) : (a2p + (k0 - 512));
        #pragma unroll
        for (int i = 0; i < 4; i++) {
            const int id = tid + 256 * i;
            const int row = id >> 3, c = id & 7;
            const uint32_t sw = (row << 7) | ((c ^ (row & 7)) << 4);
            cp16s(sb + SAH(s) + sw, base + (size_t)row * 512 + c * 8);
            cp16s(sb + SBB(s) + sw, Bb + (size_t)row * K + k0 + c * 8);
        }
        asm volatile("cp.async.commit_group;");
    };

    load_stage(0, 0);
    load_stage(1, 1);

    const int lrow = lane & 15;
    const int lhi  = lane >> 4;
    const int lph  = lane & 7;
    const uint32_t aRow0 = (uint32_t)(wm * 32 + lrow) << 7;
    const uint32_t bRow0 = (uint32_t)(wn * 64 + lrow) << 7;

    int s = 0;
    for (int kt = 0; kt < KT; kt++) {
        if (kt + 2 < KT) {
            int s2 = s + 2; if (s2 >= 3) s2 -= 3;
            load_stage(s2, kt + 2);
            asm volatile("cp.async.wait_group 2;");
        } else if (kt + 1 < KT) {
            asm volatile("cp.async.wait_group 1;");
        } else {
            asm volatile("cp.async.wait_group 0;");
        }
        __syncthreads();
        const uint32_t aH = sb + SAH(s);
        const uint32_t bS = sb + SBB(s);

        #pragma unroll
        for (int kq = 0; kq < 4; kq++) {
            const uint32_t cb = (uint32_t)(((kq * 2 + lhi) ^ lph) << 4);
            uint32_t ah[2][4], b[4][4];
            #pragma unroll
            for (int mi = 0; mi < 2; mi++)
                ldmx4(aH + aRow0 + (uint32_t)(mi * 2048) + cb, ah[mi][0], ah[mi][1], ah[mi][2], ah[mi][3]);
            #pragma unroll
            for (int n2 = 0; n2 < 4; n2++)
                ldmx4(bS + bRow0 + (uint32_t)(n2 * 2048) + cb, b[n2][0], b[n2][1], b[n2][2], b[n2][3]);
            #pragma unroll
            for (int mi = 0; mi < 2; mi++)
                #pragma unroll
                for (int ni = 0; ni < 8; ni++)
                    MMA16(acc[mi][ni], ah[mi][0], ah[mi][1], ah[mi][2], ah[mi][3],
                          b[ni >> 1][ni & 1], b[ni >> 1][2 + (ni & 1)]);
        }
        __syncthreads();
        if (++s >= 3) s -= 3;
    }

    #pragma unroll
    for (int mi = 0; mi < 2; mi++) {
        #pragma unroll
        for (int ni = 0; ni < 8; ni++) {
            const int r0 = bm * 128 + wm * 32 + mi * 16 + (lane >> 2);
            const int c  = bn * 128 + wn * 64 + ni * 8 + (lane & 3) * 2;
            epi_store<MODE>(out + (size_t)r0 * 512,       c, acc[mi][ni][0], acc[mi][ni][1], bz, lo_off);
            epi_store<MODE>(out + (size_t)(r0 + 8) * 512, c, acc[mi][ni][2], acc[mi][ni][3], bz, lo_off);
        }
    }
}

// ---------------- final tiny projections ----------------
__global__ void head2_kernel(
    const float* __restrict__ hsW2, const float* __restrict__ hsb2,
    const float* __restrict__ heW2, const float* __restrict__ heb2,
    const float* __restrict__ hfW2, const float* __restrict__ hfb2,
    const float* __restrict__ hwW2, const float* __restrict__ hwb2,
    float* __restrict__ out)
{
    int row  = blockIdx.x * 8 + (threadIdx.x >> 5);
    int lane = threadIdx.x & 31;
    const __half* h0 = g_HEADH + (size_t)row * 512;
    const __half* h1 = g_HEADH + NE + (size_t)row * 512;
    const __half* h2 = g_HEADH + 2 * NE + (size_t)row * 512;
    const __half* h3 = g_HEADH + 3 * NE + (size_t)row * 512;
    float acc[7] = {0.f, 0.f, 0.f, 0.f, 0.f, 0.f, 0.f};
    for (int k = lane; k < 512; k += 32) {
        float x0 = __half2float(h0[k]);
        float x1 = __half2float(h1[k]);
        float x2 = __half2float(h2[k]);
        float x3 = __half2float(h3[k]);
        acc[0] = fmaf(x0, hsW2[k * 3 + 0], acc[0]);
        acc[1] = fmaf(x0, hsW2[k * 3 + 1], acc[1]);
        acc[2] = fmaf(x0, hsW2[k * 3 + 2], acc[2]);
        acc[3] = fmaf(x1, heW2[k],         acc[3]);
        acc[4] = fmaf(x2, hfW2[k],         acc[4]);
        acc[5] = fmaf(x3, hwW2[k * 2 + 0], acc[5]);
        acc[6] = fmaf(x3, hwW2[k * 2 + 1], acc[6]);
    }
    #pragma unroll
    for (int j = 0; j < 7; j++)
        #pragma unroll
        for (int o = 16; o > 0; o >>= 1)
            acc[j] += __shfl_xor_sync(0xffffffffu, acc[j], o);
    if (lane == 0) {
        float* orow = out + (size_t)row * 7;
        orow[0] = acc[0] + hsb2[0];
        orow[1] = acc[1] + hsb2[1];
        orow[2] = acc[2] + hsb2[2];
        orow[3] = acc[3] + heb2[0];
        orow[4] = acc[4] + hfb2[0];
        orow[5] = acc[5] + hwb2[0];
        orow[6] = acc[6] + hwb2[1];
    }
}

// ---------------- host launch ----------------
extern "C" void kernel_launch(void* const* d_in, const int* in_sizes, int n_in,
                              void* d_out, int out_size) {
    (void)in_sizes; (void)n_in; (void)out_size;
    const float* sh    = (const float*)d_in[0];
    const float* el    = (const float*)d_in[1];
    const float* fa    = (const float*)d_in[2];
    const float* wr    = (const float*)d_in[3];
    const float* s2e_W = (const float*)d_in[4];
    const float* s2e_b = (const float*)d_in[5];
    const float* tf_W  = (const float*)d_in[6];
    const float* tf_b  = (const float*)d_in[7];
    const float* fw_W  = (const float*)d_in[8];
    const float* fw_b  = (const float*)d_in[9];
    const float* fg_W  = (const float*)d_in[10];
    const float* fg_b  = (const float*)d_in[11];
    const float* wg_W  = (const float*)d_in[12];
    const float* wg_b  = (const float*)d_in[13];
    const float* hsW1  = (const float*)d_in[14];
    const float* hsb1  = (const float*)d_in[15];
    const float* hsW2  = (const float*)d_in[16];
    const float* hsb2  = (const float*)d_in[17];
    const float* heW1  = (const float*)d_in[18];
    const float* heb1  = (const float*)d_in[19];
    const float* heW2  = (const float*)d_in[20];
    const float* heb2  = (const float*)d_in[21];
    const float* hfW1  = (const float*)d_in[22];
    const float* hfb1  = (const float*)d_in[23];
    const float* hfW2  = (const float*)d_in[24];
    const float* hfb2  = (const float*)d_in[25];
    const float* hwW1  = (const float*)d_in[26];
    const float* hwb1  = (const float*)d_in[27];
    const float* hwW2  = (const float*)d_in[28];
    const float* hwb2  = (const float*)d_in[29];

    __half *WP, *SH, *E, *FM, *GF, *F, *WM, *GW, *W4, *P, *HEADH;
    cudaGetSymbolAddress((void**)&WP,    g_WP);
    cudaGetSymbolAddress((void**)&SH,    g_SH);
    cudaGetSymbolAddress((void**)&E,     g_E);
    cudaGetSymbolAddress((void**)&FM,    g_FM);
    cudaGetSymbolAddress((void**)&GF,    g_GF);
    cudaGetSymbolAddress((void**)&F,     g_F);
    cudaGetSymbolAddress((void**)&WM,    g_WM);
    cudaGetSymbolAddress((void**)&GW,    g_GW);
    cudaGetSymbolAddress((void**)&W4,    g_W4);
    cudaGetSymbolAddress((void**)&P,     g_P);
    cudaGetSymbolAddress((void**)&HEADH, g_HEADH);

    cudaFuncSetAttribute(gemm_lm<MODE_PLAIN>, cudaFuncAttributeMaxDynamicSharedMemorySize, GEMM_SMEM);
    cudaFuncSetAttribute(gemm_lm<MODE_HILO>,  cudaFuncAttributeMaxDynamicSharedMemorySize, GEMM_SMEM);
    cudaFuncSetAttribute(gemm_lm<MODE_SIG>,   cudaFuncAttributeMaxDynamicSharedMemorySize, GEMM_SMEM);
    cudaFuncSetAttribute(gemm_lm<MODE_GELU>,  cudaFuncAttributeMaxDynamicSharedMemorySize, GEMM_SMEM);

    auto hp5_base = [](const __half* b, size_t zs) { HP5 h; for (int z = 0; z < 5; z++) h.p[z] = b + z * zs; return h; };
    auto fp5_base = [](const float* b) { FP5 f; for (int z = 0; z < 5; z++) f.p[z] = b + z * 512; return f; };

    HP5 SH5 = hp5_base(SH, 0);
    HP5 E5  = hp5_base(E,  NE);
    HP5 FM5 = hp5_base(FM, NE);
    HP5 F5  = hp5_base(F,  NE);
    HP5 WM5 = hp5_base(WM, NE);

    const int EW_GRID = (int)(NE / 256);
    dim3 g5(BATCH / 128, 4, 5);
    dim3 g4(BATCH / 128, 4, 4);

    // setup
    split_inputs_kernel<<<EW_GRID, 256>>>(sh, el, fa, wr);
    {
        PackJob j{};
        for (int i = 0; i < 5; i++) {
            j.src[i]     = s2e_W + (size_t)i * 512 * 512; j.dst[i]     = S2E_OFF + i * S2E_SZ;
            j.src[5 + i] = fg_W  + (size_t)i * 512 * 512; j.dst[5 + i] = FG_OFF  + i * S2E_SZ;
        }
        pack_multi<<<dim3(16, 16, 10), 256>>>(j, 512, 0);
    }
    {
        PackJob j{};
        for (int i = 0; i < 5; i++) { j.src[i] = wg_W + (size_t)i * 512 * 512; j.dst[i] = WG_OFF + i * S2E_SZ; }
        j.src[5] = hsW1; j.dst[5] = H1_OFF + 0 * S2E_SZ;
        j.src[6] = heW1; j.dst[6] = H1_OFF + 1 * S2E_SZ;
        j.src[7] = hfW1; j.dst[7] = H1_OFF + 2 * S2E_SZ;
        j.src[8] = hwW1; j.dst[8] = H1_OFF + 3 * S2E_SZ;
        pack_multi<<<dim3(16, 16, 9), 256>>>(j, 512, 0);
    }
    {
        PackJob j{};
        for (int i = 0; i < 5; i++) { j.src[i] = tf_W + (size_t)i * 1024 * 512; j.dst[i] = TF_OFF + i * TF_SZ; }
        pack_multi<<<dim3(32, 16, 5), 256>>>(j, 1024, 512);   // swap halves: [e | sh]
    }
    {
        PackJob j{};
        for (int i = 0; i < 5; i++) { j.src[i] = fw_W + (size_t)i * 1024 * 512; j.dst[i] = FW_OFF + i * TF_SZ; }
        pack_multi<<<dim3(32, 16, 5), 256>>>(j, 1024, 0);     // natural order: [e | f]
    }

    // A: P_z = sh @ s2eW_z + b_z   (hi+lo)
    gemm_lm<MODE_HILO><<<g5, 256, GEMM_SMEM>>>(
        SH5, SH5, WP + S2E_OFF, S2E_SZ, 512, fp5_base(s2e_b), P, (unsigned)NE, (int)(5 * NE));
    // e_z cumulative sums
    ecumsum_kernel<<<EW_GRID, 256>>>();
    // B: fm_z = [e_z | sh] @ tfW'_z + tf_b_z
    gemm_lm<MODE_PLAIN><<<g5, 256, GEMM_SMEM>>>(
        E5, SH5, WP + TF_OFF, TF_SZ, 1024, fp5_base(tf_b), FM, (unsigned)NE, 0);
    // C: gf_z = sigmoid(fm_z @ fgW_z + fg_b_z)
    gemm_lm<MODE_SIG><<<g5, 256, GEMM_SMEM>>>(
        FM5, FM5, WP + FG_OFF, S2E_SZ, 512, fp5_base(fg_b), GF, (unsigned)NE, 0);
    // f chain
    fchain_kernel<<<EW_GRID, 256>>>();
    // D: wm_z = [e_z | f_z] @ fwW_z + fw_b_z
    gemm_lm<MODE_PLAIN><<<g5, 256, GEMM_SMEM>>>(
        E5, F5, WP + FW_OFF, TF_SZ, 1024, fp5_base(fw_b), WM, (unsigned)NE, 0);
    // E: gw_z = sigmoid(wm_z @ wgW_z + wg_b_z)
    gemm_lm<MODE_SIG><<<g5, 256, GEMM_SMEM>>>(
        WM5, WM5, WP + WG_OFF, S2E_SZ, 512, fp5_base(wg_b), GW, (unsigned)NE, 0);
    // w chain
    wchain_kernel<<<EW_GRID, 256>>>();

    // heads: hidden_j = gelu(x_j @ W1_j + b1_j)
    {
        HP5 ha; ha.p[0] = SH; ha.p[1] = E + 4 * NE; ha.p[2] = F + 4 * NE; ha.p[3] = W4; ha.p[4] = SH;
        FP5 hb; hb.p[0] = hsb1; hb.p[1] = heb1; hb.p[2] = hfb1; hb.p[3] = hwb1; hb.p[4] = hsb1;
        gemm_lm<MODE_GELU><<<g4, 256, GEMM_SMEM>>>(
            ha, ha, WP + H1_OFF, S2E_SZ, 512, hb, HEADH, (unsigned)NE, 0);
    }

    head2_kernel<<<BATCH / 8, 256>>>(hsW2, hsb2, heW2, heb2, hfW2, hfb2,
                                     hwW2, hwb2, (float*)d_out);
}

// round 13
// speedup vs baseline: 1.7926x; 1.0412x over previous
#include <cuda_runtime.h>
#include <cuda_fp16.h>
#include <cstdint>
#include <cmath>

#define BATCH 32768
#define NE ((size_t)BATCH * 512)

// ---------------- packed weights ----------------
#define S2E_SZ (512*512)
#define TF_SZ  (512*1024)
#define S2E_OFF 0
#define TF_OFF  (S2E_OFF + 5*S2E_SZ)
#define FG_OFF  (TF_OFF  + 5*TF_SZ)
#define FW_OFF  (FG_OFF  + 5*S2E_SZ)
#define WG_OFF  (FW_OFF  + 5*TF_SZ)
#define H1_OFF  (WG_OFF  + 5*S2E_SZ)
#define WP_TOTAL (H1_OFF + 4*S2E_SZ)

__device__ __half g_WP[WP_TOTAL];
__device__ float  g_CB[5 * 512];          // cumulative s2e bias
__device__ __half g_SH[NE];
__device__ __half g_EIN[2 * NE];          // e0 hi | lo
__device__ __half g_FIN[2 * NE];
__device__ __half g_WIN[2 * NE];
__device__ __half g_E[5 * NE];
__device__ __half g_FM[5 * NE];
__device__ __half g_GF[5 * NE];
__device__ __half g_F[5 * NE];
__device__ __half g_WM[5 * NE];
__device__ __half g_GW[5 * NE];
__device__ __half g_W4[NE];
__device__ __half g_HEADH[4 * NE];

struct PackJob { const float* src[10]; unsigned dst[10]; };
struct GArg8 {
    const __half* a1[8];
    const __half* a2[8];
    const __half* w[8];
    const float*  bias[8];
    __half*       out[8];
    int           mode[8];   // used by MIX: 0=sigmoid, 1=gelu
};

// ---------------- helpers ----------------
__device__ __forceinline__ void cp16s(uint32_t sa, const void* g) {
    asm volatile("cp.async.cg.shared.global [%0], [%1], 16;" :: "r"(sa), "l"(g));
}
__device__ __forceinline__ void ldmx4(uint32_t addr, uint32_t& r0, uint32_t& r1, uint32_t& r2, uint32_t& r3) {
    asm volatile("ldmatrix.sync.aligned.m8n8.x4.shared.b16 {%0,%1,%2,%3}, [%4];"
        : "=r"(r0), "=r"(r1), "=r"(r2), "=r"(r3) : "r"(addr));
}
#define MMA16(acc, a0,a1,a2,a3, b0,b1) \
    asm volatile("mma.sync.aligned.m16n8k16.row.col.f32.f16.f16.f32 " \
        "{%0,%1,%2,%3},{%4,%5,%6,%7},{%8,%9},{%0,%1,%2,%3};" \
        : "+f"((acc)[0]), "+f"((acc)[1]), "+f"((acc)[2]), "+f"((acc)[3]) \
        : "r"(a0), "r"(a1), "r"(a2), "r"(a3), "r"(b0), "r"(b1))

// ---------------- setup kernels ----------------
__global__ void split_inputs_kernel(const float* __restrict__ sh, const float* __restrict__ e,
                                    const float* __restrict__ f,  const float* __restrict__ w) {
    size_t i = (size_t)blockIdx.x * 256 + threadIdx.x;
    if (i >= NE) return;
    float v; __half h;
    g_SH[i] = __float2half(sh[i]);
    v = e[i]; h = __float2half(v); g_EIN[i] = h; g_EIN[NE + i] = __float2half(v - __half2float(h));
    v = f[i]; h = __float2half(v); g_FIN[i] = h; g_FIN[NE + i] = __float2half(v - __half2float(h));
    v = w[i]; h = __float2half(v); g_WIN[i] = h; g_WIN[NE + i] = __float2half(v - __half2float(h));
}

// tiled transpose pack: fp32 W[K][512] -> fp16 g_WP[dst + n*K + (k^xmask)]
__global__ void pack_multi(PackJob job, int K, int xmask) {
    __shared__ float t[32][33];
    int k0 = blockIdx.x * 32, n0 = blockIdx.y * 32, j = blockIdx.z;
    const float* Wl = job.src[j];
    __half* ol = g_WP + job.dst[j];
    int r = threadIdx.x >> 5, c = threadIdx.x & 31;
    #pragma unroll
    for (int i = 0; i < 4; i++)
        t[r + 8 * i][c] = Wl[(size_t)(k0 + r + 8 * i) * 512 + n0 + c];
    __syncthreads();
    #pragma unroll
    for (int i = 0; i < 4; i++) {
        int n = n0 + r + 8 * i;
        ol[(size_t)n * K + ((k0 + c) ^ xmask)] = __float2half(t[c][r + 8 * i]);
    }
}

// cumulative pack for s2e: Wc_z = sum_{j<=z} W_j (fp32), transposed, fp16
__global__ void pack_cumsum(const float* __restrict__ W) {
    __shared__ float t[32][33];
    int k0 = blockIdx.x * 32, n0 = blockIdx.y * 32;
    int r = threadIdx.x >> 5, c = threadIdx.x & 31;
    float acc[4] = {0.f, 0.f, 0.f, 0.f};
    for (int z = 0; z < 5; z++) {
        const float* Wl = W + (size_t)z * 512 * 512;
        #pragma unroll
        for (int i = 0; i < 4; i++)
            t[r + 8 * i][c] = Wl[(size_t)(k0 + r + 8 * i) * 512 + n0 + c];
        __syncthreads();
        #pragma unroll
        for (int i = 0; i < 4; i++) {
            acc[i] += t[c][r + 8 * i];
            int n = n0 + r + 8 * i;
            g_WP[S2E_OFF + (size_t)z * S2E_SZ + (size_t)n * 512 + k0 + c] = __float2half(acc[i]);
        }
        __syncthreads();
    }
}

__global__ void cumbias_kernel(const float* __restrict__ b) {
    int j = threadIdx.x;   // 512 threads
    float s = 0.f;
    for (int z = 0; z < 5; z++) {
        s += b[z * 512 + j];
        g_CB[z * 512 + j] = s;
    }
}

// ---------------- elementwise chains ----------------
__global__ void fchain_kernel() {
    size_t i = (size_t)blockIdx.x * 256 + threadIdx.x;
    if (i >= NE) return;
    float f = __half2float(g_FIN[i]) + __half2float(g_FIN[NE + i]);
    #pragma unroll
    for (int z = 0; z < 5; z++) {
        float g  = __half2float(g_GF[(size_t)z * NE + i]);
        float fm = __half2float(g_FM[(size_t)z * NE + i]);
        f = f + (fm - f) * g;
        g_F[(size_t)z * NE + i] = __float2half(f);
    }
}
__global__ void wchain_kernel() {
    size_t i = (size_t)blockIdx.x * 256 + threadIdx.x;
    if (i >= NE) return;
    float w = __half2float(g_WIN[i]) + __half2float(g_WIN[NE + i]);
    #pragma unroll
    for (int z = 0; z < 5; z++) {
        float g  = __half2float(g_GW[(size_t)z * NE + i]);
        float wm = __half2float(g_WM[(size_t)z * NE + i]);
        w = w + (wm - w) * g;
    }
    g_W4[i] = __float2half(w);
}

// ---------------- GEMM ----------------
#define MODE_PLAIN 0
#define MODE_SIG   2
#define MODE_EADD  4
#define MODE_MIX   5

// M=128 x N=128 CTA tile. smem per stage: A 16K + B 16K = 32K; 3 stages = 96K
#define SAH(s) ((s) * 32768)
#define SBB(s) ((s) * 32768 + 16384)
#define GEMM_SMEM 98304

template<int MODE>
__global__ void __launch_bounds__(256, 2) gemm_lm(GArg8 g, int K)
{
    extern __shared__ __align__(1024) char dsm[];
    const uint32_t sb = (uint32_t)__cvta_generic_to_shared(dsm);
    const int tid = threadIdx.x, lane = tid & 31, warp = tid >> 5;
    const int wm = warp >> 1, wn = warp & 1;
    const int bm = blockIdx.x, bn = blockIdx.y;
    const int z  = blockIdx.z;
    const int KT = K >> 6;

    const __half* a1p = g.a1[z] + (size_t)bm * 128 * 512;
    const __half* a2p = g.a2[z] + (size_t)bm * 128 * 512;
    const __half* Bb  = g.w[z]  + (size_t)bn * 128 * K;
    const float*  bias = g.bias[z];
    __half* out = g.out[z];
    const int zmode = (MODE == MODE_MIX) ? g.mode[z] : 0;

    float acc[2][8][4];
    #pragma unroll
    for (int i = 0; i < 2; i++)
        #pragma unroll
        for (int j = 0; j < 8; j++)
            #pragma unroll
            for (int q = 0; q < 4; q++) acc[i][j][q] = 0.f;

    auto load_stage = [&](int s, int kt) {
        const int k0 = kt << 6;
        const __half* base = (k0 < 512) ? (a1p + k0) : (a2p + (k0 - 512));
        #pragma unroll
        for (int i = 0; i < 4; i++) {
            const int id = tid + 256 * i;
            const int row = id >> 3, c = id & 7;
            const uint32_t sw = (row << 7) | ((c ^ (row & 7)) << 4);
            cp16s(sb + SAH(s) + sw, base + (size_t)row * 512 + c * 8);
            cp16s(sb + SBB(s) + sw, Bb + (size_t)row * K + k0 + c * 8);
        }
        asm volatile("cp.async.commit_group;");
    };

    load_stage(0, 0);
    load_stage(1, 1);

    const int lrow = lane & 15;
    const int lhi  = lane >> 4;
    const int lph  = lane & 7;
    const uint32_t aRow0 = (uint32_t)(wm * 32 + lrow) << 7;
    const uint32_t bRow0 = (uint32_t)(wn * 64 + lrow) << 7;

    int s = 0;
    for (int kt = 0; kt < KT; kt++) {
        if (kt + 2 < KT) {
            int s2 = s + 2; if (s2 >= 3) s2 -= 3;
            load_stage(s2, kt + 2);
            asm volatile("cp.async.wait_group 2;");
        } else if (kt + 1 < KT) {
            asm volatile("cp.async.wait_group 1;");
        } else {
            asm volatile("cp.async.wait_group 0;");
        }
        __syncthreads();
        const uint32_t aH = sb + SAH(s);
        const uint32_t bS = sb + SBB(s);

        #pragma unroll
        for (int kq = 0; kq < 4; kq++) {
            const uint32_t cb = (uint32_t)(((kq * 2 + lhi) ^ lph) << 4);
            uint32_t ah[2][4], b[4][4];
            #pragma unroll
            for (int mi = 0; mi < 2; mi++)
                ldmx4(aH + aRow0 + (uint32_t)(mi * 2048) + cb, ah[mi][0], ah[mi][1], ah[mi][2], ah[mi][3]);
            #pragma unroll
            for (int n2 = 0; n2 < 4; n2++)
                ldmx4(bS + bRow0 + (uint32_t)(n2 * 2048) + cb, b[n2][0], b[n2][1], b[n2][2], b[n2][3]);
            #pragma unroll
            for (int mi = 0; mi < 2; mi++)
                #pragma unroll
                for (int ni = 0; ni < 8; ni++)
                    MMA16(acc[mi][ni], ah[mi][0], ah[mi][1], ah[mi][2], ah[mi][3],
                          b[ni >> 1][ni & 1], b[ni >> 1][2 + (ni & 1)]);
        }
        __syncthreads();
        if (++s >= 3) s -= 3;
    }

    auto epi = [&](int r, int c, float v0, float v1) {
        v0 += bias[c];
        v1 += bias[c + 1];
        if (MODE == MODE_SIG || (MODE == MODE_MIX && zmode == 0)) {
            v0 = 1.f / (1.f + expf(-v0));
            v1 = 1.f / (1.f + expf(-v1));
        } else if (MODE == MODE_MIX && zmode == 1) {
            v0 = 0.5f * v0 * (1.f + erff(v0 * 0.70710678118654752f));
            v1 = 0.5f * v1 * (1.f + erff(v1 * 0.70710678118654752f));
        } else if (MODE == MODE_EADD) {
            const __half* xr = g_EIN + (size_t)r * 512;
            __half2 xh = *(const __half2*)(xr + c);
            __half2 xl = *(const __half2*)(xr + NE + c);
            v0 += __half2float(xh.x) + __half2float(xl.x);
            v1 += __half2float(xh.y) + __half2float(xl.y);
        }
        __half2 hh;
        hh.x = __float2half(v0);
        hh.y = __float2half(v1);
        *(__half2*)(out + (size_t)r * 512 + c) = hh;
    };

    #pragma unroll
    for (int mi = 0; mi < 2; mi++) {
        #pragma unroll
        for (int ni = 0; ni < 8; ni++) {
            const int r0 = bm * 128 + wm * 32 + mi * 16 + (lane >> 2);
            const int c  = bn * 128 + wn * 64 + ni * 8 + (lane & 3) * 2;
            epi(r0,     c, acc[mi][ni][0], acc[mi][ni][1]);
            epi(r0 + 8, c, acc[mi][ni][2], acc[mi][ni][3]);
        }
    }
}

// ---------------- final tiny projections ----------------
__global__ void head2_kernel(
    const float* __restrict__ hsW2, const float* __restrict__ hsb2,
    const float* __restrict__ heW2, const float* __restrict__ heb2,
    const float* __restrict__ hfW2, const float* __restrict__ hfb2,
    const float* __restrict__ hwW2, const float* __restrict__ hwb2,
    float* __restrict__ out)
{
    int row  = blockIdx.x * 8 + (threadIdx.x >> 5);
    int lane = threadIdx.x & 31;
    const __half* h0 = g_HEADH + (size_t)row * 512;
    const __half* h1 = g_HEADH + NE + (size_t)row * 512;
    const __half* h2 = g_HEADH + 2 * NE + (size_t)row * 512;
    const __half* h3 = g_HEADH + 3 * NE + (size_t)row * 512;
    float acc[7] = {0.f, 0.f, 0.f, 0.f, 0.f, 0.f, 0.f};
    for (int k = lane; k < 512; k += 32) {
        float x0 = __half2float(h0[k]);
        float x1 = __half2float(h1[k]);
        float x2 = __half2float(h2[k]);
        float x3 = __half2float(h3[k]);
        acc[0] = fmaf(x0, hsW2[k * 3 + 0], acc[0]);
        acc[1] = fmaf(x0, hsW2[k * 3 + 1], acc[1]);
        acc[2] = fmaf(x0, hsW2[k * 3 + 2], acc[2]);
        acc[3] = fmaf(x1, heW2[k],         acc[3]);
        acc[4] = fmaf(x2, hfW2[k],         acc[4]);
        acc[5] = fmaf(x3, hwW2[k * 2 + 0], acc[5]);
        acc[6] = fmaf(x3, hwW2[k * 2 + 1], acc[6]);
    }
    #pragma unroll
    for (int j = 0; j < 7; j++)
        #pragma unroll
        for (int o = 16; o > 0; o >>= 1)
            acc[j] += __shfl_xor_sync(0xffffffffu, acc[j], o);
    if (lane == 0) {
        float* orow = out + (size_t)row * 7;
        orow[0] = acc[0] + hsb2[0];
        orow[1] = acc[1] + hsb2[1];
        orow[2] = acc[2] + hsb2[2];
        orow[3] = acc[3] + heb2[0];
        orow[4] = acc[4] + hfb2[0];
        orow[5] = acc[5] + hwb2[0];
        orow[6] = acc[6] + hwb2[1];
    }
}

// ---------------- host launch ----------------
extern "C" void kernel_launch(void* const* d_in, const int* in_sizes, int n_in,
                              void* d_out, int out_size) {
    (void)in_sizes; (void)n_in; (void)out_size;
    const float* sh    = (const float*)d_in[0];
    const float* el    = (const float*)d_in[1];
    const float* fa    = (const float*)d_in[2];
    const float* wr    = (const float*)d_in[3];
    const float* s2e_W = (const float*)d_in[4];
    const float* s2e_b = (const float*)d_in[5];
    const float* tf_W  = (const float*)d_in[6];
    const float* tf_b  = (const float*)d_in[7];
    const float* fw_W  = (const float*)d_in[8];
    const float* fw_b  = (const float*)d_in[9];
    const float* fg_W  = (const float*)d_in[10];
    const float* fg_b  = (const float*)d_in[11];
    const float* wg_W  = (const float*)d_in[12];
    const float* wg_b  = (const float*)d_in[13];
    const float* hsW1  = (const float*)d_in[14];
    const float* hsb1  = (const float*)d_in[15];
    const float* hsW2  = (const float*)d_in[16];
    const float* hsb2  = (const float*)d_in[17];
    const float* heW1  = (const float*)d_in[18];
    const float* heb1  = (const float*)d_in[19];
    const float* heW2  = (const float*)d_in[20];
    const float* heb2  = (const float*)d_in[21];
    const float* hfW1  = (const float*)d_in[22];
    const float* hfb1  = (const float*)d_in[23];
    const float* hfW2  = (const float*)d_in[24];
    const float* hfb2  = (const float*)d_in[25];
    const float* hwW1  = (const float*)d_in[26];
    const float* hwb1  = (const float*)d_in[27];
    const float* hwW2  = (const float*)d_in[28];
    const float* hwb2  = (const float*)d_in[29];

    __half *WP, *SH, *E, *FM, *GF, *F, *WM, *GW, *W4, *HEADH;
    float* CB;
    cudaGetSymbolAddress((void**)&WP,    g_WP);
    cudaGetSymbolAddress((void**)&CB,    g_CB);
    cudaGetSymbolAddress((void**)&SH,    g_SH);
    cudaGetSymbolAddress((void**)&E,     g_E);
    cudaGetSymbolAddress((void**)&FM,    g_FM);
    cudaGetSymbolAddress((void**)&GF,    g_GF);
    cudaGetSymbolAddress((void**)&F,     g_F);
    cudaGetSymbolAddress((void**)&WM,    g_WM);
    cudaGetSymbolAddress((void**)&GW,    g_GW);
    cudaGetSymbolAddress((void**)&W4,    g_W4);
    cudaGetSymbolAddress((void**)&HEADH, g_HEADH);

    cudaFuncSetAttribute(gemm_lm<MODE_PLAIN>, cudaFuncAttributeMaxDynamicSharedMemorySize, GEMM_SMEM);
    cudaFuncSetAttribute(gemm_lm<MODE_SIG>,   cudaFuncAttributeMaxDynamicSharedMemorySize, GEMM_SMEM);
    cudaFuncSetAttribute(gemm_lm<MODE_EADD>,  cudaFuncAttributeMaxDynamicSharedMemorySize, GEMM_SMEM);
    cudaFuncSetAttribute(gemm_lm<MODE_MIX>,   cudaFuncAttributeMaxDynamicSharedMemorySize, GEMM_SMEM);

    const int EW_GRID = (int)(NE / 256);

    // ---------------- setup ----------------
    split_inputs_kernel<<<EW_GRID, 256>>>(sh, el, fa, wr);
    pack_cumsum<<<dim3(16, 16), 256>>>(s2e_W);
    cumbias_kernel<<<1, 512>>>(s2e_b);
    {
        PackJob j{};
        for (int i = 0; i < 5; i++) {
            j.src[i]     = fg_W + (size_t)i * 512 * 512; j.dst[i]     = FG_OFF + i * S2E_SZ;
            j.src[5 + i] = wg_W + (size_t)i * 512 * 512; j.dst[5 + i] = WG_OFF + i * S2E_SZ;
        }
        pack_multi<<<dim3(16, 16, 10), 256>>>(j, 512, 0);
    }
    {
        PackJob j{};
        j.src[0] = hsW1; j.dst[0] = H1_OFF + 0 * S2E_SZ;
        j.src[1] = heW1; j.dst[1] = H1_OFF + 1 * S2E_SZ;
        j.src[2] = hfW1; j.dst[2] = H1_OFF + 2 * S2E_SZ;
        j.src[3] = hwW1; j.dst[3] = H1_OFF + 3 * S2E_SZ;
        pack_multi<<<dim3(16, 16, 4), 256>>>(j, 512, 0);
    }
    {
        PackJob j{};
        for (int i = 0; i < 5; i++) { j.src[i] = tf_W + (size_t)i * 1024 * 512; j.dst[i] = TF_OFF + i * TF_SZ; }
        pack_multi<<<dim3(32, 16, 5), 256>>>(j, 1024, 512);   // [e | sh]
    }
    {
        PackJob j{};
        for (int i = 0; i < 5; i++) { j.src[i] = fw_W + (size_t)i * 1024 * 512; j.dst[i] = FW_OFF + i * TF_SZ; }
        pack_multi<<<dim3(32, 16, 5), 256>>>(j, 1024, 0);     // [e | f]
    }

    dim3 g5(BATCH / 128, 4, 5);
    dim3 g8(BATCH / 128, 4, 8);
    dim3 g1(BATCH / 128, 4, 1);

    // ---------------- GEMM chain ----------------
    // A: e_z = e0 + sh @ Wc_z + bc_z
    {
        GArg8 a{};
        for (int z = 0; z < 5; z++) {
            a.a1[z] = SH; a.a2[z] = SH;
            a.w[z]  = WP + S2E_OFF + (size_t)z * S2E_SZ;
            a.bias[z] = CB + z * 512;
            a.out[z]  = E + (size_t)z * NE;
        }
        gemm_lm<MODE_EADD><<<g5, 256, GEMM_SMEM>>>(a, 512);
    }
    // B: fm_z = [e_z | sh] @ tfW'_z + tf_b_z
    {
        GArg8 a{};
        for (int z = 0; z < 5; z++) {
            a.a1[z] = E + (size_t)z * NE; a.a2[z] = SH;
            a.w[z]  = WP + TF_OFF + (size_t)z * TF_SZ;
            a.bias[z] = tf_b + z * 512;
            a.out[z]  = FM + (size_t)z * NE;
        }
        gemm_lm<MODE_PLAIN><<<g5, 256, GEMM_SMEM>>>(a, 1024);
    }
    // C: gf_z = sigmoid(fm_z @ fgW_z + fg_b_z)
    {
        GArg8 a{};
        for (int z = 0; z < 5; z++) {
            a.a1[z] = FM + (size_t)z * NE; a.a2[z] = FM + (size_t)z * NE;
            a.w[z]  = WP + FG_OFF + (size_t)z * S2E_SZ;
            a.bias[z] = fg_b + z * 512;
            a.out[z]  = GF + (size_t)z * NE;
        }
        gemm_lm<MODE_SIG><<<g5, 256, GEMM_SMEM>>>(a, 512);
    }
    fchain_kernel<<<EW_GRID, 256>>>();
    // D: wm_z = [e_z | f_z] @ fwW_z + fw_b_z
    {
        GArg8 a{};
        for (int z = 0; z < 5; z++) {
            a.a1[z] = E + (size_t)z * NE; a.a2[z] = F + (size_t)z * NE;
            a.w[z]  = WP + FW_OFF + (size_t)z * TF_SZ;
            a.bias[z] = fw_b + z * 512;
            a.out[z]  = WM + (size_t)z * NE;
        }
        gemm_lm<MODE_PLAIN><<<g5, 256, GEMM_SMEM>>>(a, 1024);
    }
    // E + heads(sh,e,f): z0-4 sigmoid(wm@wgW) -> GW; z5-7 gelu(x@W1) -> HEADH
    {
        GArg8 a{};
        for (int z = 0; z < 5; z++) {
            a.a1[z] = WM + (size_t)z * NE; a.a2[z] = WM + (size_t)z * NE;
            a.w[z]  = WP + WG_OFF + (size_t)z * S2E_SZ;
            a.bias[z] = wg_b + z * 512;
            a.out[z]  = GW + (size_t)z * NE;
            a.mode[z] = 0;
        }
        a.a1[5] = SH;          a.a2[5] = SH;          a.w[5] = WP + H1_OFF + 0 * S2E_SZ; a.bias[5] = hsb1; a.out[5] = HEADH;          a.mode[5] = 1;
        a.a1[6] = E + 4 * NE;  a.a2[6] = E + 4 * NE;  a.w[6] = WP + H1_OFF + 1 * S2E_SZ; a.bias[6] = heb1; a.out[6] = HEADH + NE;     a.mode[6] = 1;
        a.a1[7] = F + 4 * NE;  a.a2[7] = F + 4 * NE;  a.w[7] = WP + H1_OFF + 2 * S2E_SZ; a.bias[7] = hfb1; a.out[7] = HEADH + 2 * NE; a.mode[7] = 1;
        gemm_lm<MODE_MIX><<<g8, 256, GEMM_SMEM>>>(a, 512);
    }
    wchain_kernel<<<EW_GRID, 256>>>();
    // hw head: gelu(w4 @ hwW1 + b)
    {
        GArg8 a{};
        a.a1[0] = W4; a.a2[0] = W4;
        a.w[0]  = WP + H1_OFF + 3 * S2E_SZ;
        a.bias[0] = hwb1;
        a.out[0]  = HEADH + 3 * NE;
        a.mode[0] = 1;
        gemm_lm<MODE_MIX><<<g1, 256, GEMM_SMEM>>>(a, 512);
    }

    head2_kernel<<<BATCH / 8, 256>>>(hsW2, hsb2, heW2, heb2, hfW2, hfb2,
                                     hwW2, hwb2, (float*)d_out);
}

// round 14
// speedup vs baseline: 1.9429x; 1.0839x over previous
#include <cuda_runtime.h>
#include <cuda_fp16.h>
#include <cstdint>
#include <cmath>

#define BATCH 32768
#define NE ((size_t)BATCH * 512)

// ---------------- packed weights ----------------
#define S2E_SZ (512*512)
#define TF_SZ  (512*1024)
#define S2E_OFF 0
#define TF_OFF  (S2E_OFF + 5*S2E_SZ)
#define FG_OFF  (TF_OFF  + 5*TF_SZ)
#define FW_OFF  (FG_OFF  + 5*S2E_SZ)
#define WG_OFF  (FW_OFF  + 5*TF_SZ)
#define H1_OFF  (WG_OFF  + 5*S2E_SZ)
#define WP_TOTAL (H1_OFF + 4*S2E_SZ)

__device__ __half g_WP[WP_TOTAL];
__device__ float  g_CB[5 * 512];          // cumulative s2e bias
__device__ __half g_SH[NE];
__device__ __half g_E[5 * NE];
__device__ __half g_FM[5 * NE];
__device__ __half g_GF[5 * NE];
__device__ __half g_F[5 * NE];
__device__ __half g_WM[5 * NE];
__device__ __half g_GW[5 * NE];
__device__ __half g_W4[NE];
__device__ __half g_HEADH[4 * NE];

struct PackJob { const float* src[10]; unsigned dst[10]; };
struct GArg8 {
    const __half* a1[8];
    const __half* a2[8];
    const __half* w[8];
    const float*  bias[8];
    __half*       out[8];
    int           mode[8];   // used by MIX: 0=sigmoid, 1=gelu
};

// ---------------- helpers ----------------
__device__ __forceinline__ void cp16s(uint32_t sa, const void* g) {
    asm volatile("cp.async.cg.shared.global [%0], [%1], 16;" :: "r"(sa), "l"(g));
}
__device__ __forceinline__ void ldmx4(uint32_t addr, uint32_t& r0, uint32_t& r1, uint32_t& r2, uint32_t& r3) {
    asm volatile("ldmatrix.sync.aligned.m8n8.x4.shared.b16 {%0,%1,%2,%3}, [%4];"
        : "=r"(r0), "=r"(r1), "=r"(r2), "=r"(r3) : "r"(addr));
}
#define MMA16(acc, a0,a1,a2,a3, b0,b1) \
    asm volatile("mma.sync.aligned.m16n8k16.row.col.f32.f16.f16.f32 " \
        "{%0,%1,%2,%3},{%4,%5,%6,%7},{%8,%9},{%0,%1,%2,%3};" \
        : "+f"((acc)[0]), "+f"((acc)[1]), "+f"((acc)[2]), "+f"((acc)[3]) \
        : "r"(a0), "r"(a1), "r"(a2), "r"(a3), "r"(b0), "r"(b1))

// ---------------- setup kernels ----------------
__global__ void split_sh_kernel(const float* __restrict__ sh) {
    size_t i = ((size_t)blockIdx.x * 256 + threadIdx.x) * 4;
    if (i >= NE) return;
    float4 v = *(const float4*)(sh + i);
    __half2 a, b;
    a.x = __float2half(v.x); a.y = __float2half(v.y);
    b.x = __float2half(v.z); b.y = __float2half(v.w);
    *(__half2*)(g_SH + i)     = a;
    *(__half2*)(g_SH + i + 2) = b;
}

// tiled transpose pack: fp32 W[K][512] -> fp16 g_WP[dst + n*K + (k^xmask)]
__global__ void pack_multi(PackJob job, int K, int xmask) {
    __shared__ float t[32][33];
    int k0 = blockIdx.x * 32, n0 = blockIdx.y * 32, j = blockIdx.z;
    const float* Wl = job.src[j];
    __half* ol = g_WP + job.dst[j];
    int r = threadIdx.x >> 5, c = threadIdx.x & 31;
    #pragma unroll
    for (int i = 0; i < 4; i++)
        t[r + 8 * i][c] = Wl[(size_t)(k0 + r + 8 * i) * 512 + n0 + c];
    __syncthreads();
    #pragma unroll
    for (int i = 0; i < 4; i++) {
        int n = n0 + r + 8 * i;
        ol[(size_t)n * K + ((k0 + c) ^ xmask)] = __float2half(t[c][r + 8 * i]);
    }
}

// cumulative pack for s2e: Wc_z = sum_{j<=z} W_j (fp32), transposed, fp16
__global__ void pack_cumsum(const float* __restrict__ W) {
    __shared__ float t[32][33];
    int k0 = blockIdx.x * 32, n0 = blockIdx.y * 32;
    int r = threadIdx.x >> 5, c = threadIdx.x & 31;
    float acc[4] = {0.f, 0.f, 0.f, 0.f};
    for (int z = 0; z < 5; z++) {
        const float* Wl = W + (size_t)z * 512 * 512;
        #pragma unroll
        for (int i = 0; i < 4; i++)
            t[r + 8 * i][c] = Wl[(size_t)(k0 + r + 8 * i) * 512 + n0 + c];
        __syncthreads();
        #pragma unroll
        for (int i = 0; i < 4; i++) {
            acc[i] += t[c][r + 8 * i];
            int n = n0 + r + 8 * i;
            g_WP[S2E_OFF + (size_t)z * S2E_SZ + (size_t)n * 512 + k0 + c] = __float2half(acc[i]);
        }
        __syncthreads();
    }
}

__global__ void cumbias_kernel(const float* __restrict__ b) {
    int j = threadIdx.x;   // 512 threads
    float s = 0.f;
    for (int z = 0; z < 5; z++) {
        s += b[z * 512 + j];
        g_CB[z * 512 + j] = s;
    }
}

// ---------------- elementwise chains (2-wide vectorized, fp32 seed) ----------------
__global__ void fchain_kernel(const float* __restrict__ fa) {
    size_t i = ((size_t)blockIdx.x * 256 + threadIdx.x) * 2;
    if (i >= NE) return;
    float2 f0 = *(const float2*)(fa + i);
    float fA = f0.x, fB = f0.y;
    #pragma unroll
    for (int z = 0; z < 5; z++) {
        __half2 g2 = *(const __half2*)(g_GF + (size_t)z * NE + i);
        __half2 m2 = *(const __half2*)(g_FM + (size_t)z * NE + i);
        float gA = __half2float(g2.x), gB = __half2float(g2.y);
        float mA = __half2float(m2.x), mB = __half2float(m2.y);
        fA = fA + (mA - fA) * gA;
        fB = fB + (mB - fB) * gB;
        __half2 o; o.x = __float2half(fA); o.y = __float2half(fB);
        *(__half2*)(g_F + (size_t)z * NE + i) = o;
    }
}
__global__ void wchain_kernel(const float* __restrict__ wr) {
    size_t i = ((size_t)blockIdx.x * 256 + threadIdx.x) * 2;
    if (i >= NE) return;
    float2 w0 = *(const float2*)(wr + i);
    float wA = w0.x, wB = w0.y;
    #pragma unroll
    for (int z = 0; z < 5; z++) {
        __half2 g2 = *(const __half2*)(g_GW + (size_t)z * NE + i);
        __half2 m2 = *(const __half2*)(g_WM + (size_t)z * NE + i);
        float gA = __half2float(g2.x), gB = __half2float(g2.y);
        float mA = __half2float(m2.x), mB = __half2float(m2.y);
        wA = wA + (mA - wA) * gA;
        wB = wB + (mB - wB) * gB;
    }
    __half2 o; o.x = __float2half(wA); o.y = __float2half(wB);
    *(__half2*)(g_W4 + i) = o;
}

// ---------------- GEMM ----------------
#define MODE_PLAIN 0
#define MODE_SIG   2
#define MODE_EADD  4
#define MODE_MIX   5

// M=128 x N=128 CTA tile. smem per stage: A 16K + B 16K = 32K; 3 stages = 96K
#define SAH(s) ((s) * 32768)
#define SBB(s) ((s) * 32768 + 16384)
#define GEMM_SMEM 98304

template<int MODE>
__global__ void __launch_bounds__(256, 2) gemm_lm(GArg8 g, int K, const float* __restrict__ e0f)
{
    extern __shared__ __align__(1024) char dsm[];
    const uint32_t sb = (uint32_t)__cvta_generic_to_shared(dsm);
    const int tid = threadIdx.x, lane = tid & 31, warp = tid >> 5;
    const int wm = warp >> 1, wn = warp & 1;
    const int bm = blockIdx.x, bn = blockIdx.y;
    const int z  = blockIdx.z;
    const int KT = K >> 6;

    const __half* a1p = g.a1[z] + (size_t)bm * 128 * 512;
    const __half* a2p = g.a2[z] + (size_t)bm * 128 * 512;
    const __half* Bb  = g.w[z]  + (size_t)bn * 128 * K;
    const float*  bias = g.bias[z];
    __half* out = g.out[z];
    const int zmode = (MODE == MODE_MIX) ? g.mode[z] : 0;

    float acc[2][8][4];
    #pragma unroll
    for (int i = 0; i < 2; i++)
        #pragma unroll
        for (int j = 0; j < 8; j++)
            #pragma unroll
            for (int q = 0; q < 4; q++) acc[i][j][q] = 0.f;

    auto load_stage = [&](int s, int kt) {
        const int k0 = kt << 6;
        const __half* base = (k0 < 512) ? (a1p + k0) : (a2p + (k0 - 512));
        #pragma unroll
        for (int i = 0; i < 4; i++) {
            const int id = tid + 256 * i;
            const int row = id >> 3, c = id & 7;
            const uint32_t sw = (row << 7) | ((c ^ (row & 7)) << 4);
            cp16s(sb + SAH(s) + sw, base + (size_t)row * 512 + c * 8);
            cp16s(sb + SBB(s) + sw, Bb + (size_t)row * K + k0 + c * 8);
        }
        asm volatile("cp.async.commit_group;");
    };

    load_stage(0, 0);
    load_stage(1, 1);

    const int lrow = lane & 15;
    const int lhi  = lane >> 4;
    const int lph  = lane & 7;
    const uint32_t aRow0 = (uint32_t)(wm * 32 + lrow) << 7;
    const uint32_t bRow0 = (uint32_t)(wn * 64 + lrow) << 7;

    int s = 0;
    for (int kt = 0; kt < KT; kt++) {
        if (kt + 2 < KT) {
            int s2 = s + 2; if (s2 >= 3) s2 -= 3;
            load_stage(s2, kt + 2);
            asm volatile("cp.async.wait_group 2;");
        } else if (kt + 1 < KT) {
            asm volatile("cp.async.wait_group 1;");
        } else {
            asm volatile("cp.async.wait_group 0;");
        }
        __syncthreads();
        const uint32_t aH = sb + SAH(s);
        const uint32_t bS = sb + SBB(s);

        #pragma unroll
        for (int kq = 0; kq < 4; kq++) {
            const uint32_t cb = (uint32_t)(((kq * 2 + lhi) ^ lph) << 4);
            uint32_t ah[2][4], b[4][4];
            #pragma unroll
            for (int mi = 0; mi < 2; mi++)
                ldmx4(aH + aRow0 + (uint32_t)(mi * 2048) + cb, ah[mi][0], ah[mi][1], ah[mi][2], ah[mi][3]);
            #pragma unroll
            for (int n2 = 0; n2 < 4; n2++)
                ldmx4(bS + bRow0 + (uint32_t)(n2 * 2048) + cb, b[n2][0], b[n2][1], b[n2][2], b[n2][3]);
            #pragma unroll
            for (int mi = 0; mi < 2; mi++)
                #pragma unroll
                for (int ni = 0; ni < 8; ni++)
                    MMA16(acc[mi][ni], ah[mi][0], ah[mi][1], ah[mi][2], ah[mi][3],
                          b[ni >> 1][ni & 1], b[ni >> 1][2 + (ni & 1)]);
        }
        __syncthreads();
        if (++s >= 3) s -= 3;
    }

    auto epi = [&](int r, int c, float v0, float v1) {
        v0 += bias[c];
        v1 += bias[c + 1];
        if (MODE == MODE_SIG || (MODE == MODE_MIX && zmode == 0)) {
            v0 = 1.f / (1.f + expf(-v0));
            v1 = 1.f / (1.f + expf(-v1));
        } else if (MODE == MODE_MIX && zmode == 1) {
            v0 = 0.5f * v0 * (1.f + erff(v0 * 0.70710678118654752f));
            v1 = 0.5f * v1 * (1.f + erff(v1 * 0.70710678118654752f));
        } else if (MODE == MODE_EADD) {
            float2 e2 = *(const float2*)(e0f + (size_t)r * 512 + c);
            v0 += e2.x;
            v1 += e2.y;
        }
        __half2 hh;
        hh.x = __float2half(v0);
        hh.y = __float2half(v1);
        *(__half2*)(out + (size_t)r * 512 + c) = hh;
    };

    #pragma unroll
    for (int mi = 0; mi < 2; mi++) {
        #pragma unroll
        for (int ni = 0; ni < 8; ni++) {
            const int r0 = bm * 128 + wm * 32 + mi * 16 + (lane >> 2);
            const int c  = bn * 128 + wn * 64 + ni * 8 + (lane & 3) * 2;
            epi(r0,     c, acc[mi][ni][0], acc[mi][ni][1]);
            epi(r0 + 8, c, acc[mi][ni][2], acc[mi][ni][3]);
        }
    }
}

// ---------------- final tiny projections ----------------
__global__ void head2_kernel(
    const float* __restrict__ hsW2, const float* __restrict__ hsb2,
    const float* __restrict__ heW2, const float* __restrict__ heb2,
    const float* __restrict__ hfW2, const float* __restrict__ hfb2,
    const float* __restrict__ hwW2, const float* __restrict__ hwb2,
    float* __restrict__ out)
{
    int row  = blockIdx.x * 8 + (threadIdx.x >> 5);
    int lane = threadIdx.x & 31;
    const __half* h0 = g_HEADH + (size_t)row * 512;
    const __half* h1 = g_HEADH + NE + (size_t)row * 512;
    const __half* h2 = g_HEADH + 2 * NE + (size_t)row * 512;
    const __half* h3 = g_HEADH + 3 * NE + (size_t)row * 512;
    float acc[7] = {0.f, 0.f, 0.f, 0.f, 0.f, 0.f, 0.f};
    for (int k = lane; k < 512; k += 32) {
        float x0 = __half2float(h0[k]);
        float x1 = __half2float(h1[k]);
        float x2 = __half2float(h2[k]);
        float x3 = __half2float(h3[k]);
        acc[0] = fmaf(x0, hsW2[k * 3 + 0], acc[0]);
        acc[1] = fmaf(x0, hsW2[k * 3 + 1], acc[1]);
        acc[2] = fmaf(x0, hsW2[k * 3 + 2], acc[2]);
        acc[3] = fmaf(x1, heW2[k],         acc[3]);
        acc[4] = fmaf(x2, hfW2[k],         acc[4]);
        acc[5] = fmaf(x3, hwW2[k * 2 + 0], acc[5]);
        acc[6] = fmaf(x3, hwW2[k * 2 + 1], acc[6]);
    }
    #pragma unroll
    for (int j = 0; j < 7; j++)
        #pragma unroll
        for (int o = 16; o > 0; o >>= 1)
            acc[j] += __shfl_xor_sync(0xffffffffu, acc[j], o);
    if (lane == 0) {
        float* orow = out + (size_t)row * 7;
        orow[0] = acc[0] + hsb2[0];
        orow[1] = acc[1] + hsb2[1];
        orow[2] = acc[2] + hsb2[2];
        orow[3] = acc[3] + heb2[0];
        orow[4] = acc[4] + hfb2[0];
        orow[5] = acc[5] + hwb2[0];
        orow[6] = acc[6] + hwb2[1];
    }
}

// ---------------- host launch ----------------
extern "C" void kernel_launch(void* const* d_in, const int* in_sizes, int n_in,
                              void* d_out, int out_size) {
    (void)in_sizes; (void)n_in; (void)out_size;
    const float* sh    = (const float*)d_in[0];
    const float* el    = (const float*)d_in[1];
    const float* fa    = (const float*)d_in[2];
    const float* wr    = (const float*)d_in[3];
    const float* s2e_W = (const float*)d_in[4];
    const float* s2e_b = (const float*)d_in[5];
    const float* tf_W  = (const float*)d_in[6];
    const float* tf_b  = (const float*)d_in[7];
    const float* fw_W  = (const float*)d_in[8];
    const float* fw_b  = (const float*)d_in[9];
    const float* fg_W  = (const float*)d_in[10];
    const float* fg_b  = (const float*)d_in[11];
    const float* wg_W  = (const float*)d_in[12];
    const float* wg_b  = (const float*)d_in[13];
    const float* hsW1  = (const float*)d_in[14];
    const float* hsb1  = (const float*)d_in[15];
    const float* hsW2  = (const float*)d_in[16];
    const float* hsb2  = (const float*)d_in[17];
    const float* heW1  = (const float*)d_in[18];
    const float* heb1  = (const float*)d_in[19];
    const float* heW2  = (const float*)d_in[20];
    const float* heb2  = (const float*)d_in[21];
    const float* hfW1  = (const float*)d_in[22];
    const float* hfb1  = (const float*)d_in[23];
    const float* hfW2  = (const float*)d_in[24];
    const float* hfb2  = (const float*)d_in[25];
    const float* hwW1  = (const float*)d_in[26];
    const float* hwb1  = (const float*)d_in[27];
    const float* hwW2  = (const float*)d_in[28];
    const float* hwb2  = (const float*)d_in[29];

    __half *WP, *SH, *E, *FM, *GF, *F, *WM, *GW, *W4, *HEADH;
    float* CB;
    cudaGetSymbolAddress((void**)&WP,    g_WP);
    cudaGetSymbolAddress((void**)&CB,    g_CB);
    cudaGetSymbolAddress((void**)&SH,    g_SH);
    cudaGetSymbolAddress((void**)&E,     g_E);
    cudaGetSymbolAddress((void**)&FM,    g_FM);
    cudaGetSymbolAddress((void**)&GF,    g_GF);
    cudaGetSymbolAddress((void**)&F,     g_F);
    cudaGetSymbolAddress((void**)&WM,    g_WM);
    cudaGetSymbolAddress((void**)&GW,    g_GW);
    cudaGetSymbolAddress((void**)&W4,    g_W4);
    cudaGetSymbolAddress((void**)&HEADH, g_HEADH);

    cudaFuncSetAttribute(gemm_lm<MODE_PLAIN>, cudaFuncAttributeMaxDynamicSharedMemorySize, GEMM_SMEM);
    cudaFuncSetAttribute(gemm_lm<MODE_SIG>,   cudaFuncAttributeMaxDynamicSharedMemorySize, GEMM_SMEM);
    cudaFuncSetAttribute(gemm_lm<MODE_EADD>,  cudaFuncAttributeMaxDynamicSharedMemorySize, GEMM_SMEM);
    cudaFuncSetAttribute(gemm_lm<MODE_MIX>,   cudaFuncAttributeMaxDynamicSharedMemorySize, GEMM_SMEM);

    const int EW2_GRID = (int)(NE / 512);

    // ---------------- setup ----------------
    split_sh_kernel<<<(int)(NE / 1024), 256>>>(sh);
    pack_cumsum<<<dim3(16, 16), 256>>>(s2e_W);
    cumbias_kernel<<<1, 512>>>(s2e_b);
    {
        PackJob j{};
        for (int i = 0; i < 5; i++) {
            j.src[i]     = fg_W + (size_t)i * 512 * 512; j.dst[i]     = FG_OFF + i * S2E_SZ;
            j.src[5 + i] = wg_W + (size_t)i * 512 * 512; j.dst[5 + i] = WG_OFF + i * S2E_SZ;
        }
        pack_multi<<<dim3(16, 16, 10), 256>>>(j, 512, 0);
    }
    {
        PackJob j{};
        j.src[0] = hsW1; j.dst[0] = H1_OFF + 0 * S2E_SZ;
        j.src[1] = heW1; j.dst[1] = H1_OFF + 1 * S2E_SZ;
        j.src[2] = hfW1; j.dst[2] = H1_OFF + 2 * S2E_SZ;
        j.src[3] = hwW1; j.dst[3] = H1_OFF + 3 * S2E_SZ;
        pack_multi<<<dim3(16, 16, 4), 256>>>(j, 512, 0);
    }
    {
        PackJob j{};
        for (int i = 0; i < 5; i++) { j.src[i] = tf_W + (size_t)i * 1024 * 512; j.dst[i] = TF_OFF + i * TF_SZ; }
        pack_multi<<<dim3(32, 16, 5), 256>>>(j, 1024, 512);   // [e | sh]
    }
    {
        PackJob j{};
        for (int i = 0; i < 5; i++) { j.src[i] = fw_W + (size_t)i * 1024 * 512; j.dst[i] = FW_OFF + i * TF_SZ; }
        pack_multi<<<dim3(32, 16, 5), 256>>>(j, 1024, 0);     // [e | f]
    }

    dim3 g5(BATCH / 128, 4, 5);
    dim3 g8(BATCH / 128, 4, 8);
    dim3 g1(BATCH / 128, 4, 1);

    // ---------------- GEMM chain ----------------
    // A: e_z = e0 + sh @ Wc_z + bc_z
    {
        GArg8 a{};
        for (int z = 0; z < 5; z++) {
            a.a1[z] = SH; a.a2[z] = SH;
            a.w[z]  = WP + S2E_OFF + (size_t)z * S2E_SZ;
            a.bias[z] = CB + z * 512;
            a.out[z]  = E + (size_t)z * NE;
        }
        gemm_lm<MODE_EADD><<<g5, 256, GEMM_SMEM>>>(a, 512, el);
    }
    // B: fm_z = [e_z | sh] @ tfW'_z + tf_b_z
    {
        GArg8 a{};
        for (int z = 0; z < 5; z++) {
            a.a1[z] = E + (size_t)z * NE; a.a2[z] = SH;
            a.w[z]  = WP + TF_OFF + (size_t)z * TF_SZ;
            a.bias[z] = tf_b + z * 512;
            a.out[z]  = FM + (size_t)z * NE;
        }
        gemm_lm<MODE_PLAIN><<<g5, 256, GEMM_SMEM>>>(a, 1024, nullptr);
    }
    // C: gf_z = sigmoid(fm_z @ fgW_z + fg_b_z)
    {
        GArg8 a{};
        for (int z = 0; z < 5; z++) {
            a.a1[z] = FM + (size_t)z * NE; a.a2[z] = FM + (size_t)z * NE;
            a.w[z]  = WP + FG_OFF + (size_t)z * S2E_SZ;
            a.bias[z] = fg_b + z * 512;
            a.out[z]  = GF + (size_t)z * NE;
        }
        gemm_lm<MODE_SIG><<<g5, 256, GEMM_SMEM>>>(a, 512, nullptr);
    }
    fchain_kernel<<<EW2_GRID, 256>>>(fa);
    // D: wm_z = [e_z | f_z] @ fwW_z + fw_b_z
    {
        GArg8 a{};
        for (int z = 0; z < 5; z++) {
            a.a1[z] = E + (size_t)z * NE; a.a2[z] = F + (size_t)z * NE;
            a.w[z]  = WP + FW_OFF + (size_t)z * TF_SZ;
            a.bias[z] = fw_b + z * 512;
            a.out[z]  = WM + (size_t)z * NE;
        }
        gemm_lm<MODE_PLAIN><<<g5, 256, GEMM_SMEM>>>(a, 1024, nullptr);
    }
    // E + heads(sh,e,f): z0-4 sigmoid(wm@wgW) -> GW; z5-7 gelu(x@W1) -> HEADH
    {
        GArg8 a{};
        for (int z = 0; z < 5; z++) {
            a.a1[z] = WM + (size_t)z * NE; a.a2[z] = WM + (size_t)z * NE;
            a.w[z]  = WP + WG_OFF + (size_t)z * S2E_SZ;
            a.bias[z] = wg_b + z * 512;
            a.out[z]  = GW + (size_t)z * NE;
            a.mode[z] = 0;
        }
        a.a1[5] = SH;          a.a2[5] = SH;          a.w[5] = WP + H1_OFF + 0 * S2E_SZ; a.bias[5] = hsb1; a.out[5] = HEADH;          a.mode[5] = 1;
        a.a1[6] = E + 4 * NE;  a.a2[6] = E + 4 * NE;  a.w[6] = WP + H1_OFF + 1 * S2E_SZ; a.bias[6] = heb1; a.out[6] = HEADH + NE;     a.mode[6] = 1;
        a.a1[7] = F + 4 * NE;  a.a2[7] = F + 4 * NE;  a.w[7] = WP + H1_OFF + 2 * S2E_SZ; a.bias[7] = hfb1; a.out[7] = HEADH + 2 * NE; a.mode[7] = 1;
        gemm_lm<MODE_MIX><<<g8, 256, GEMM_SMEM>>>(a, 512, nullptr);
    }
    wchain_kernel<<<EW2_GRID, 256>>>(wr);
    // hw head: gelu(w4 @ hwW1 + b)
    {
        GArg8 a{};
        a.a1[0] = W4; a.a2[0] = W4;
        a.w[0]  = WP + H1_OFF + 3 * S2E_SZ;
        a.bias[0] = hwb1;
        a.out[0]  = HEADH + 3 * NE;
        a.mode[0] = 1;
        gemm_lm<MODE_MIX><<<g1, 256, GEMM_SMEM>>>(a, 512, nullptr);
    }

    head2_kernel<<<BATCH / 8, 256>>>(hsW2, hsb2, heW2, heb2, hfW2, hfb2,
                                     hwW2, hwb2, (float*)d_out);
}

// round 15
// speedup vs baseline: 1.9984x; 1.0286x over previous
#include <cuda_runtime.h>
#include <cuda_fp16.h>
#include <cstdint>
#include <cmath>

#define BATCH 32768
#define NE ((size_t)BATCH * 512)

// ---------------- packed weights ----------------
#define S2E_SZ (512*512)
#define TF_SZ  (512*1024)
#define S2E_OFF 0
#define TF_OFF  (S2E_OFF + 5*S2E_SZ)
#define FG_OFF  (TF_OFF  + 5*TF_SZ)
#define FW_OFF  (FG_OFF  + 5*S2E_SZ)
#define WG_OFF  (FW_OFF  + 5*TF_SZ)
#define H1_OFF  (WG_OFF  + 5*S2E_SZ)
#define WP_TOTAL (H1_OFF + 4*S2E_SZ)

__device__ __half g_WP[WP_TOTAL];
__device__ float  g_CB[5 * 512];          // cumulative s2e bias
__device__ __half g_SH[NE];
__device__ __half g_E[5 * NE];
__device__ __half g_FM[5 * NE];
__device__ __half g_GF[5 * NE];
__device__ __half g_F[5 * NE];
__device__ __half g_WM[5 * NE];
__device__ __half g_GW[5 * NE];
__device__ __half g_W4[NE];
__device__ __half g_HEADH[4 * NE];

struct PackAll { const float* src[24]; unsigned dst[24]; int K[24]; int xmask[24]; };
struct GArg8 {
    const __half* a1[8];
    const __half* a2[8];
    const __half* w[8];
    const float*  bias[8];
    __half*       out[8];
    int           mode[8];   // used by MIX: 0=sigmoid, 1=gelu
};

// ---------------- helpers ----------------
__device__ __forceinline__ void cp16s(uint32_t sa, const void* g) {
    asm volatile("cp.async.cg.shared.global [%0], [%1], 16;" :: "r"(sa), "l"(g));
}
__device__ __forceinline__ void ldmx4(uint32_t addr, uint32_t& r0, uint32_t& r1, uint32_t& r2, uint32_t& r3) {
    asm volatile("ldmatrix.sync.aligned.m8n8.x4.shared.b16 {%0,%1,%2,%3}, [%4];"
        : "=r"(r0), "=r"(r1), "=r"(r2), "=r"(r3) : "r"(addr));
}
#define MMA16(acc, a0,a1,a2,a3, b0,b1) \
    asm volatile("mma.sync.aligned.m16n8k16.row.col.f32.f16.f16.f32 " \
        "{%0,%1,%2,%3},{%4,%5,%6,%7},{%8,%9},{%0,%1,%2,%3};" \
        : "+f"((acc)[0]), "+f"((acc)[1]), "+f"((acc)[2]), "+f"((acc)[3]) \
        : "r"(a0), "r"(a1), "r"(a2), "r"(a3), "r"(b0), "r"(b1))

// ---------------- setup kernels ----------------
__global__ void split_sh_kernel(const float* __restrict__ sh) {
    size_t i = ((size_t)blockIdx.x * 256 + threadIdx.x) * 4;
    if (i >= NE) return;
    float4 v = *(const float4*)(sh + i);
    __half2 a, b;
    a.x = __float2half(v.x); a.y = __float2half(v.y);
    b.x = __float2half(v.z); b.y = __float2half(v.w);
    *(__half2*)(g_SH + i)     = a;
    *(__half2*)(g_SH + i + 2) = b;
}

// all non-cumulative packs in one launch
__global__ void pack_all(PackAll job) {
    __shared__ float t[32][33];
    const int j = blockIdx.z;
    const int K = job.K[j];
    const int k0 = blockIdx.x * 32;
    if (k0 >= K) return;
    const int n0 = blockIdx.y * 32;
    const int xmask = job.xmask[j];
    const float* Wl = job.src[j];
    __half* ol = g_WP + job.dst[j];
    int r = threadIdx.x >> 5, c = threadIdx.x & 31;
    #pragma unroll
    for (int i = 0; i < 4; i++)
        t[r + 8 * i][c] = Wl[(size_t)(k0 + r + 8 * i) * 512 + n0 + c];
    __syncthreads();
    #pragma unroll
    for (int i = 0; i < 4; i++) {
        int n = n0 + r + 8 * i;
        ol[(size_t)n * K + ((k0 + c) ^ xmask)] = __float2half(t[c][r + 8 * i]);
    }
}

// cumulative pack for s2e: Wc_z = sum_{j<=z} W_j (fp32), transposed, fp16
__global__ void pack_cumsum(const float* __restrict__ W) {
    __shared__ float t[32][33];
    int k0 = blockIdx.x * 32, n0 = blockIdx.y * 32;
    int r = threadIdx.x >> 5, c = threadIdx.x & 31;
    float acc[4] = {0.f, 0.f, 0.f, 0.f};
    for (int z = 0; z < 5; z++) {
        const float* Wl = W + (size_t)z * 512 * 512;
        #pragma unroll
        for (int i = 0; i < 4; i++)
            t[r + 8 * i][c] = Wl[(size_t)(k0 + r + 8 * i) * 512 + n0 + c];
        __syncthreads();
        #pragma unroll
        for (int i = 0; i < 4; i++) {
            acc[i] += t[c][r + 8 * i];
            int n = n0 + r + 8 * i;
            g_WP[S2E_OFF + (size_t)z * S2E_SZ + (size_t)n * 512 + k0 + c] = __float2half(acc[i]);
        }
        __syncthreads();
    }
}

__global__ void cumbias_kernel(const float* __restrict__ b) {
    int j = threadIdx.x;   // 512 threads
    float s = 0.f;
    for (int z = 0; z < 5; z++) {
        s += b[z * 512 + j];
        g_CB[z * 512 + j] = s;
    }
}

// ---------------- elementwise chains (4-wide, fp32 seed) ----------------
__global__ void fchain_kernel(const float* __restrict__ fa) {
    size_t i = ((size_t)blockIdx.x * 256 + threadIdx.x) * 4;
    if (i >= NE) return;
    float4 f0 = *(const float4*)(fa + i);
    float f[4] = { f0.x, f0.y, f0.z, f0.w };
    #pragma unroll
    for (int z = 0; z < 5; z++) {
        uint2 gv = *(const uint2*)(g_GF + (size_t)z * NE + i);
        uint2 mv = *(const uint2*)(g_FM + (size_t)z * NE + i);
        const __half2* g2 = (const __half2*)&gv;
        const __half2* m2 = (const __half2*)&mv;
        uint2 ov;
        __half2* o2 = (__half2*)&ov;
        #pragma unroll
        for (int q = 0; q < 2; q++) {
            float2 gq = __half22float2(g2[q]);
            float2 mq = __half22float2(m2[q]);
            f[2 * q]     += (mq.x - f[2 * q])     * gq.x;
            f[2 * q + 1] += (mq.y - f[2 * q + 1]) * gq.y;
            o2[q].x = __float2half(f[2 * q]);
            o2[q].y = __float2half(f[2 * q + 1]);
        }
        *(uint2*)(g_F + (size_t)z * NE + i) = ov;
    }
}
__global__ void wchain_kernel(const float* __restrict__ wr) {
    size_t i = ((size_t)blockIdx.x * 256 + threadIdx.x) * 4;
    if (i >= NE) return;
    float4 w0 = *(const float4*)(wr + i);
    float w[4] = { w0.x, w0.y, w0.z, w0.w };
    #pragma unroll
    for (int z = 0; z < 5; z++) {
        uint2 gv = *(const uint2*)(g_GW + (size_t)z * NE + i);
        uint2 mv = *(const uint2*)(g_WM + (size_t)z * NE + i);
        const __half2* g2 = (const __half2*)&gv;
        const __half2* m2 = (const __half2*)&mv;
        #pragma unroll
        for (int q = 0; q < 2; q++) {
            float2 gq = __half22float2(g2[q]);
            float2 mq = __half22float2(m2[q]);
            w[2 * q]     += (mq.x - w[2 * q])     * gq.x;
            w[2 * q + 1] += (mq.y - w[2 * q + 1]) * gq.y;
        }
    }
    uint2 ov;
    __half2* o2 = (__half2*)&ov;
    o2[0].x = __float2half(w[0]); o2[0].y = __float2half(w[1]);
    o2[1].x = __float2half(w[2]); o2[1].y = __float2half(w[3]);
    *(uint2*)(g_W4 + i) = ov;
}

// ---------------- GEMM ----------------
#define MODE_PLAIN 0
#define MODE_SIG   2
#define MODE_EADD  4
#define MODE_MIX   5

// M=128 x N=128 CTA tile. smem per stage: A 16K + B 16K = 32K; 3 stages = 96K
#define SAH(s) ((s) * 32768)
#define SBB(s) ((s) * 32768 + 16384)
#define GEMM_SMEM 98304

template<int MODE>
__global__ void __launch_bounds__(256, 2) gemm_lm(GArg8 g, int K, const float* __restrict__ e0f)
{
    extern __shared__ __align__(1024) char dsm[];
    const uint32_t sb = (uint32_t)__cvta_generic_to_shared(dsm);
    const int tid = threadIdx.x, lane = tid & 31, warp = tid >> 5;
    const int wm = warp >> 1, wn = warp & 1;
    const int bm = blockIdx.x, bn = blockIdx.y;
    const int z  = blockIdx.z;
    const int KT = K >> 6;

    const __half* a1p = g.a1[z] + (size_t)bm * 128 * 512;
    const __half* a2p = g.a2[z] + (size_t)bm * 128 * 512;
    const __half* Bb  = g.w[z]  + (size_t)bn * 128 * K;
    const float*  bias = g.bias[z];
    __half* out = g.out[z];
    const int zmode = (MODE == MODE_MIX) ? g.mode[z] : 0;

    float acc[2][8][4];
    #pragma unroll
    for (int i = 0; i < 2; i++)
        #pragma unroll
        for (int j = 0; j < 8; j++)
            #pragma unroll
            for (int q = 0; q < 4; q++) acc[i][j][q] = 0.f;

    auto load_stage = [&](int s, int kt) {
        const int k0 = kt << 6;
        const __half* base = (k0 < 512) ? (a1p + k0) : (a2p + (k0 - 512));
        #pragma unroll
        for (int i = 0; i < 4; i++) {
            const int id = tid + 256 * i;
            const int row = id >> 3, c = id & 7;
            const uint32_t sw = (row << 7) | ((c ^ (row & 7)) << 4);
            cp16s(sb + SAH(s) + sw, base + (size_t)row * 512 + c * 8);
            cp16s(sb + SBB(s) + sw, Bb + (size_t)row * K + k0 + c * 8);
        }
        asm volatile("cp.async.commit_group;");
    };

    load_stage(0, 0);
    load_stage(1, 1);

    const int lrow = lane & 15;
    const int lhi  = lane >> 4;
    const int lph  = lane & 7;
    const uint32_t aRow0 = (uint32_t)(wm * 32 + lrow) << 7;
    const uint32_t bRow0 = (uint32_t)(wn * 64 + lrow) << 7;

    int s = 0;
    for (int kt = 0; kt < KT; kt++) {
        if (kt + 2 < KT) {
            int s2 = s + 2; if (s2 >= 3) s2 -= 3;
            load_stage(s2, kt + 2);
            asm volatile("cp.async.wait_group 2;");
        } else if (kt + 1 < KT) {
            asm volatile("cp.async.wait_group 1;");
        } else {
            asm volatile("cp.async.wait_group 0;");
        }
        __syncthreads();
        const uint32_t aH = sb + SAH(s);
        const uint32_t bS = sb + SBB(s);

        #pragma unroll
        for (int kq = 0; kq < 4; kq++) {
            const uint32_t cb = (uint32_t)(((kq * 2 + lhi) ^ lph) << 4);
            uint32_t ah[2][4], b[4][4];
            #pragma unroll
            for (int mi = 0; mi < 2; mi++)
                ldmx4(aH + aRow0 + (uint32_t)(mi * 2048) + cb, ah[mi][0], ah[mi][1], ah[mi][2], ah[mi][3]);
            #pragma unroll
            for (int n2 = 0; n2 < 4; n2++)
                ldmx4(bS + bRow0 + (uint32_t)(n2 * 2048) + cb, b[n2][0], b[n2][1], b[n2][2], b[n2][3]);
            #pragma unroll
            for (int mi = 0; mi < 2; mi++)
                #pragma unroll
                for (int ni = 0; ni < 8; ni++)
                    MMA16(acc[mi][ni], ah[mi][0], ah[mi][1], ah[mi][2], ah[mi][3],
                          b[ni >> 1][ni & 1], b[ni >> 1][2 + (ni & 1)]);
        }
        __syncthreads();
        if (++s >= 3) s -= 3;
    }

    auto epi = [&](int r, int c, float v0, float v1) {
        v0 += bias[c];
        v1 += bias[c + 1];
        if (MODE == MODE_SIG || (MODE == MODE_MIX && zmode == 0)) {
            v0 = 1.f / (1.f + expf(-v0));
            v1 = 1.f / (1.f + expf(-v1));
        } else if (MODE == MODE_MIX && zmode == 1) {
            v0 = 0.5f * v0 * (1.f + erff(v0 * 0.70710678118654752f));
            v1 = 0.5f * v1 * (1.f + erff(v1 * 0.70710678118654752f));
        } else if (MODE == MODE_EADD) {
            float2 e2 = *(const float2*)(e0f + (size_t)r * 512 + c);
            v0 += e2.x;
            v1 += e2.y;
        }
        __half2 hh;
        hh.x = __float2half(v0);
        hh.y = __float2half(v1);
        *(__half2*)(out + (size_t)r * 512 + c) = hh;
    };

    #pragma unroll
    for (int mi = 0; mi < 2; mi++) {
        #pragma unroll
        for (int ni = 0; ni < 8; ni++) {
            const int r0 = bm * 128 + wm * 32 + mi * 16 + (lane >> 2);
            const int c  = bn * 128 + wn * 64 + ni * 8 + (lane & 3) * 2;
            epi(r0,     c, acc[mi][ni][0], acc[mi][ni][1]);
            epi(r0 + 8, c, acc[mi][ni][2], acc[mi][ni][3]);
        }
    }
}

// ---------------- final tiny projections ----------------
__global__ void head2_kernel(
    const float* __restrict__ hsW2, const float* __restrict__ hsb2,
    const float* __restrict__ heW2, const float* __restrict__ heb2,
    const float* __restrict__ hfW2, const float* __restrict__ hfb2,
    const float* __restrict__ hwW2, const float* __restrict__ hwb2,
    float* __restrict__ out)
{
    int row  = blockIdx.x * 8 + (threadIdx.x >> 5);
    int lane = threadIdx.x & 31;
    const __half* h0 = g_HEADH + (size_t)row * 512;
    const __half* h1 = g_HEADH + NE + (size_t)row * 512;
    const __half* h2 = g_HEADH + 2 * NE + (size_t)row * 512;
    const __half* h3 = g_HEADH + 3 * NE + (size_t)row * 512;
    float acc[7] = {0.f, 0.f, 0.f, 0.f, 0.f, 0.f, 0.f};
    for (int k = lane; k < 512; k += 32) {
        float x0 = __half2float(h0[k]);
        float x1 = __half2float(h1[k]);
        float x2 = __half2float(h2[k]);
        float x3 = __half2float(h3[k]);
        acc[0] = fmaf(x0, hsW2[k * 3 + 0], acc[0]);
        acc[1] = fmaf(x0, hsW2[k * 3 + 1], acc[1]);
        acc[2] = fmaf(x0, hsW2[k * 3 + 2], acc[2]);
        acc[3] = fmaf(x1, heW2[k],         acc[3]);
        acc[4] = fmaf(x2, hfW2[k],         acc[4]);
        acc[5] = fmaf(x3, hwW2[k * 2 + 0], acc[5]);
        acc[6] = fmaf(x3, hwW2[k * 2 + 1], acc[6]);
    }
    #pragma unroll
    for (int j = 0; j < 7; j++)
        #pragma unroll
        for (int o = 16; o > 0; o >>= 1)
            acc[j] += __shfl_xor_sync(0xffffffffu, acc[j], o);
    if (lane == 0) {
        float* orow = out + (size_t)row * 7;
        orow[0] = acc[0] + hsb2[0];
        orow[1] = acc[1] + hsb2[1];
        orow[2] = acc[2] + hsb2[2];
        orow[3] = acc[3] + heb2[0];
        orow[4] = acc[4] + hfb2[0];
        orow[5] = acc[5] + hwb2[0];
        orow[6] = acc[6] + hwb2[1];
    }
}

// ---------------- host launch ----------------
extern "C" void kernel_launch(void* const* d_in, const int* in_sizes, int n_in,
                              void* d_out, int out_size) {
    (void)in_sizes; (void)n_in; (void)out_size;
    const float* sh    = (const float*)d_in[0];
    const float* el    = (const float*)d_in[1];
    const float* fa    = (const float*)d_in[2];
    const float* wr    = (const float*)d_in[3];
    const float* s2e_W = (const float*)d_in[4];
    const float* s2e_b = (const float*)d_in[5];
    const float* tf_W  = (const float*)d_in[6];
    const float* tf_b  = (const float*)d_in[7];
    const float* fw_W  = (const float*)d_in[8];
    const float* fw_b  = (const float*)d_in[9];
    const float* fg_W  = (const float*)d_in[10];
    const float* fg_b  = (const float*)d_in[11];
    const float* wg_W  = (const float*)d_in[12];
    const float* wg_b  = (const float*)d_in[13];
    const float* hsW1  = (const float*)d_in[14];
    const float* hsb1  = (const float*)d_in[15];
    const float* hsW2  = (const float*)d_in[16];
    const float* hsb2  = (const float*)d_in[17];
    const float* heW1  = (const float*)d_in[18];
    const float* heb1  = (const float*)d_in[19];
    const float* heW2  = (const float*)d_in[20];
    const float* heb2  = (const float*)d_in[21];
    const float* hfW1  = (const float*)d_in[22];
    const float* hfb1  = (const float*)d_in[23];
    const float* hfW2  = (const float*)d_in[24];
    const float* hfb2  = (const float*)d_in[25];
    const float* hwW1  = (const float*)d_in[26];
    const float* hwb1  = (const float*)d_in[27];
    const float* hwW2  = (const float*)d_in[28];
    const float* hwb2  = (const float*)d_in[29];

    __half *WP, *SH, *E, *FM, *GF, *F, *WM, *GW, *W4, *HEADH;
    float* CB;
    cudaGetSymbolAddress((void**)&WP,    g_WP);
    cudaGetSymbolAddress((void**)&CB,    g_CB);
    cudaGetSymbolAddress((void**)&SH,    g_SH);
    cudaGetSymbolAddress((void**)&E,     g_E);
    cudaGetSymbolAddress((void**)&FM,    g_FM);
    cudaGetSymbolAddress((void**)&GF,    g_GF);
    cudaGetSymbolAddress((void**)&F,     g_F);
    cudaGetSymbolAddress((void**)&WM,    g_WM);
    cudaGetSymbolAddress((void**)&GW,    g_GW);
    cudaGetSymbolAddress((void**)&W4,    g_W4);
    cudaGetSymbolAddress((void**)&HEADH, g_HEADH);

    cudaFuncSetAttribute(gemm_lm<MODE_PLAIN>, cudaFuncAttributeMaxDynamicSharedMemorySize, GEMM_SMEM);
    cudaFuncSetAttribute(gemm_lm<MODE_SIG>,   cudaFuncAttributeMaxDynamicSharedMemorySize, GEMM_SMEM);
    cudaFuncSetAttribute(gemm_lm<MODE_EADD>,  cudaFuncAttributeMaxDynamicSharedMemorySize, GEMM_SMEM);
    cudaFuncSetAttribute(gemm_lm<MODE_MIX>,   cudaFuncAttributeMaxDynamicSharedMemorySize, GEMM_SMEM);

    const int EW4_GRID = (int)(NE / 1024);

    // ---------------- setup ----------------
    split_sh_kernel<<<(int)(NE / 1024), 256>>>(sh);
    pack_cumsum<<<dim3(16, 16), 256>>>(s2e_W);
    cumbias_kernel<<<1, 512>>>(s2e_b);
    {
        PackAll j{};
        int n = 0;
        for (int i = 0; i < 5; i++) { j.src[n] = fg_W + (size_t)i * 512 * 512; j.dst[n] = FG_OFF + i * S2E_SZ; j.K[n] = 512;  j.xmask[n] = 0;   n++; }
        for (int i = 0; i < 5; i++) { j.src[n] = wg_W + (size_t)i * 512 * 512; j.dst[n] = WG_OFF + i * S2E_SZ; j.K[n] = 512;  j.xmask[n] = 0;   n++; }
        j.src[n] = hsW1; j.dst[n] = H1_OFF + 0 * S2E_SZ; j.K[n] = 512; j.xmask[n] = 0; n++;
        j.src[n] = heW1; j.dst[n] = H1_OFF + 1 * S2E_SZ; j.K[n] = 512; j.xmask[n] = 0; n++;
        j.src[n] = hfW1; j.dst[n] = H1_OFF + 2 * S2E_SZ; j.K[n] = 512; j.xmask[n] = 0; n++;
        j.src[n] = hwW1; j.dst[n] = H1_OFF + 3 * S2E_SZ; j.K[n] = 512; j.xmask[n] = 0; n++;
        for (int i = 0; i < 5; i++) { j.src[n] = tf_W + (size_t)i * 1024 * 512; j.dst[n] = TF_OFF + i * TF_SZ; j.K[n] = 1024; j.xmask[n] = 512; n++; }  // [e | sh]
        for (int i = 0; i < 5; i++) { j.src[n] = fw_W + (size_t)i * 1024 * 512; j.dst[n] = FW_OFF + i * TF_SZ; j.K[n] = 1024; j.xmask[n] = 0;   n++; }  // [e | f]
        pack_all<<<dim3(32, 16, 24), 256>>>(j);
    }

    dim3 g5(BATCH / 128, 4, 5);
    dim3 g8(BATCH / 128, 4, 8);
    dim3 g1(BATCH / 128, 4, 1);

    // ---------------- GEMM chain ----------------
    // A: e_z = e0 + sh @ Wc_z + bc_z
    {
        GArg8 a{};
        for (int z = 0; z < 5; z++) {
            a.a1[z] = SH; a.a2[z] = SH;
            a.w[z]  = WP + S2E_OFF + (size_t)z * S2E_SZ;
            a.bias[z] = CB + z * 512;
            a.out[z]  = E + (size_t)z * NE;
        }
        gemm_lm<MODE_EADD><<<g5, 256, GEMM_SMEM>>>(a, 512, el);
    }
    // B: fm_z = [e_z | sh] @ tfW'_z + tf_b_z
    {
        GArg8 a{};
        for (int z = 0; z < 5; z++) {
            a.a1[z] = E + (size_t)z * NE; a.a2[z] = SH;
            a.w[z]  = WP + TF_OFF + (size_t)z * TF_SZ;
            a.bias[z] = tf_b + z * 512;
            a.out[z]  = FM + (size_t)z * NE;
        }
        gemm_lm<MODE_PLAIN><<<g5, 256, GEMM_SMEM>>>(a, 1024, nullptr);
    }
    // C: gf_z = sigmoid(fm_z @ fgW_z + fg_b_z)
    {
        GArg8 a{};
        for (int z = 0; z < 5; z++) {
            a.a1[z] = FM + (size_t)z * NE; a.a2[z] = FM + (size_t)z * NE;
            a.w[z]  = WP + FG_OFF + (size_t)z * S2E_SZ;
            a.bias[z] = fg_b + z * 512;
            a.out[z]  = GF + (size_t)z * NE;
        }
        gemm_lm<MODE_SIG><<<g5, 256, GEMM_SMEM>>>(a, 512, nullptr);
    }
    fchain_kernel<<<EW4_GRID, 256>>>(fa);
    // D: wm_z = [e_z | f_z] @ fwW_z + fw_b_z
    {
        GArg8 a{};
        for (int z = 0; z < 5; z++) {
            a.a1[z] = E + (size_t)z * NE; a.a2[z] = F + (size_t)z * NE;
            a.w[z]  = WP + FW_OFF + (size_t)z * TF_SZ;
            a.bias[z] = fw_b + z * 512;
            a.out[z]  = WM + (size_t)z * NE;
        }
        gemm_lm<MODE_PLAIN><<<g5, 256, GEMM_SMEM>>>(a, 1024, nullptr);
    }
    // E + heads(sh,e,f): z0-4 sigmoid(wm@wgW) -> GW; z5-7 gelu(x@W1) -> HEADH
    {
        GArg8 a{};
        for (int z = 0; z < 5; z++) {
            a.a1[z] = WM + (size_t)z * NE; a.a2[z] = WM + (size_t)z * NE;
            a.w[z]  = WP + WG_OFF + (size_t)z * S2E_SZ;
            a.bias[z] = wg_b + z * 512;
            a.out[z]  = GW + (size_t)z * NE;
            a.mode[z] = 0;
        }
        a.a1[5] = SH;          a.a2[5] = SH;          a.w[5] = WP + H1_OFF + 0 * S2E_SZ; a.bias[5] = hsb1; a.out[5] = HEADH;          a.mode[5] = 1;
        a.a1[6] = E + 4 * NE;  a.a2[6] = E + 4 * NE;  a.w[6] = WP + H1_OFF + 1 * S2E_SZ; a.bias[6] = heb1; a.out[6] = HEADH + NE;     a.mode[6] = 1;
        a.a1[7] = F + 4 * NE;  a.a2[7] = F + 4 * NE;  a.w[7] = WP + H1_OFF + 2 * S2E_SZ; a.bias[7] = hfb1; a.out[7] = HEADH + 2 * NE; a.mode[7] = 1;
        gemm_lm<MODE_MIX><<<g8, 256, GEMM_SMEM>>>(a, 512, nullptr);
    }
    wchain_kernel<<<EW4_GRID, 256>>>(wr);
    // hw head: gelu(w4 @ hwW1 + b)
    {
        GArg8 a{};
        a.a1[0] = W4; a.a2[0] = W4;
        a.w[0]  = WP + H1_OFF + 3 * S2E_SZ;
        a.bias[0] = hwb1;
        a.out[0]  = HEADH + 3 * NE;
        a.mode[0] = 1;
        gemm_lm<MODE_MIX><<<g1, 256, GEMM_SMEM>>>(a, 512, nullptr);
    }

    head2_kernel<<<BATCH / 8, 256>>>(hsW2, hsb2, heW2, heb2, hfW2, hfb2,
                                     hwW2, hwb2, (float*)d_out);
}

// round 16
// speedup vs baseline: 2.0243x; 1.0129x over previous
#include <cuda_runtime.h>
#include <cuda_fp16.h>
#include <cstdint>
#include <cmath>

#define BATCH 32768
#define NE ((size_t)BATCH * 512)

// ---------------- packed weights ----------------
#define S2E_SZ (512*512)
#define TF_SZ  (512*1024)
#define S2E_OFF 0
#define TF_OFF  (S2E_OFF + 5*S2E_SZ)
#define FG_OFF  (TF_OFF  + 5*TF_SZ)
#define FW_OFF  (FG_OFF  + 5*S2E_SZ)
#define WG_OFF  (FW_OFF  + 5*TF_SZ)
#define H1_OFF  (WG_OFF  + 5*S2E_SZ)
#define WP_TOTAL (H1_OFF + 4*S2E_SZ)

__device__ __half g_WP[WP_TOTAL];
__device__ float  g_CB[5 * 512];          // cumulative s2e bias
__device__ __half g_SH[NE];
__device__ __half g_E[5 * NE];
__device__ __half g_FM[5 * NE];
__device__ __half g_GF[5 * NE];
__device__ __half g_F[5 * NE];
__device__ __half g_WM[5 * NE];
__device__ __half g_GW[5 * NE];
__device__ __half g_W4[NE];

struct PackAll { const float* src[24]; unsigned dst[24]; int K[24]; int xmask[24]; };
struct GArg8 {
    const __half* a1[8];
    const __half* a2[8];
    const __half* w[8];
    const float*  bias[8];
    __half*       out[8];
    int           mode[8];   // MIX: 0=sigmoid->store, 1=gelu->head reduction
    const float*  w2[8];     // head second-layer weights [512][nout]
    int           nout[8];   // outputs for this head (<=3)
    int           jb[8];     // column offset into the 7-wide output
};

// ---------------- helpers ----------------
__device__ __forceinline__ void cp16s(uint32_t sa, const void* g) {
    asm volatile("cp.async.cg.shared.global [%0], [%1], 16;" :: "r"(sa), "l"(g));
}
__device__ __forceinline__ void ldmx4(uint32_t addr, uint32_t& r0, uint32_t& r1, uint32_t& r2, uint32_t& r3) {
    asm volatile("ldmatrix.sync.aligned.m8n8.x4.shared.b16 {%0,%1,%2,%3}, [%4];"
        : "=r"(r0), "=r"(r1), "=r"(r2), "=r"(r3) : "r"(addr));
}
#define MMA16(acc, a0,a1,a2,a3, b0,b1) \
    asm volatile("mma.sync.aligned.m16n8k16.row.col.f32.f16.f16.f32 " \
        "{%0,%1,%2,%3},{%4,%5,%6,%7},{%8,%9},{%0,%1,%2,%3};" \
        : "+f"((acc)[0]), "+f"((acc)[1]), "+f"((acc)[2]), "+f"((acc)[3]) \
        : "r"(a0), "r"(a1), "r"(a2), "r"(a3), "r"(b0), "r"(b1))

// ---------------- setup kernels ----------------
__global__ void split_sh_kernel(const float* __restrict__ sh) {
    size_t i = ((size_t)blockIdx.x * 256 + threadIdx.x) * 4;
    if (i >= NE) return;
    float4 v = *(const float4*)(sh + i);
    __half2 a, b;
    a.x = __float2half(v.x); a.y = __float2half(v.y);
    b.x = __float2half(v.z); b.y = __float2half(v.w);
    *(__half2*)(g_SH + i)     = a;
    *(__half2*)(g_SH + i + 2) = b;
}

__global__ void init_out_kernel(float* __restrict__ out,
    const float* __restrict__ b0, const float* __restrict__ b1,
    const float* __restrict__ b2, const float* __restrict__ b3) {
    int r = blockIdx.x * 256 + threadIdx.x;
    if (r >= BATCH) return;
    float* o = out + (size_t)r * 7;
    o[0] = b0[0]; o[1] = b0[1]; o[2] = b0[2];
    o[3] = b1[0]; o[4] = b2[0];
    o[5] = b3[0]; o[6] = b3[1];
}

// all non-cumulative packs in one launch
__global__ void pack_all(PackAll job) {
    __shared__ float t[32][33];
    const int j = blockIdx.z;
    const int K = job.K[j];
    const int k0 = blockIdx.x * 32;
    if (k0 >= K) return;
    const int n0 = blockIdx.y * 32;
    const int xmask = job.xmask[j];
    const float* Wl = job.src[j];
    __half* ol = g_WP + job.dst[j];
    int r = threadIdx.x >> 5, c = threadIdx.x & 31;
    #pragma unroll
    for (int i = 0; i < 4; i++)
        t[r + 8 * i][c] = Wl[(size_t)(k0 + r + 8 * i) * 512 + n0 + c];
    __syncthreads();
    #pragma unroll
    for (int i = 0; i < 4; i++) {
        int n = n0 + r + 8 * i;
        ol[(size_t)n * K + ((k0 + c) ^ xmask)] = __float2half(t[c][r + 8 * i]);
    }
}

// cumulative pack for s2e: Wc_z = sum_{j<=z} W_j (fp32), transposed, fp16
__global__ void pack_cumsum(const float* __restrict__ W) {
    __shared__ float t[32][33];
    int k0 = blockIdx.x * 32, n0 = blockIdx.y * 32;
    int r = threadIdx.x >> 5, c = threadIdx.x & 31;
    float acc[4] = {0.f, 0.f, 0.f, 0.f};
    for (int z = 0; z < 5; z++) {
        const float* Wl = W + (size_t)z * 512 * 512;
        #pragma unroll
        for (int i = 0; i < 4; i++)
            t[r + 8 * i][c] = Wl[(size_t)(k0 + r + 8 * i) * 512 + n0 + c];
        __syncthreads();
        #pragma unroll
        for (int i = 0; i < 4; i++) {
            acc[i] += t[c][r + 8 * i];
            int n = n0 + r + 8 * i;
            g_WP[S2E_OFF + (size_t)z * S2E_SZ + (size_t)n * 512 + k0 + c] = __float2half(acc[i]);
        }
        __syncthreads();
    }
}

__global__ void cumbias_kernel(const float* __restrict__ b) {
    int j = threadIdx.x;   // 512 threads
    float s = 0.f;
    for (int z = 0; z < 5; z++) {
        s += b[z * 512 + j];
        g_CB[z * 512 + j] = s;
    }
}

// ---------------- elementwise chains (4-wide, fp32 seed) ----------------
__global__ void fchain_kernel(const float* __restrict__ fa) {
    size_t i = ((size_t)blockIdx.x * 256 + threadIdx.x) * 4;
    if (i >= NE) return;
    float4 f0 = *(const float4*)(fa + i);
    float f[4] = { f0.x, f0.y, f0.z, f0.w };
    #pragma unroll
    for (int z = 0; z < 5; z++) {
        uint2 gv = *(const uint2*)(g_GF + (size_t)z * NE + i);
        uint2 mv = *(const uint2*)(g_FM + (size_t)z * NE + i);
        const __half2* g2 = (const __half2*)&gv;
        const __half2* m2 = (const __half2*)&mv;
        uint2 ov;
        __half2* o2 = (__half2*)&ov;
        #pragma unroll
        for (int q = 0; q < 2; q++) {
            float2 gq = __half22float2(g2[q]);
            float2 mq = __half22float2(m2[q]);
            f[2 * q]     += (mq.x - f[2 * q])     * gq.x;
            f[2 * q + 1] += (mq.y - f[2 * q + 1]) * gq.y;
            o2[q].x = __float2half(f[2 * q]);
            o2[q].y = __float2half(f[2 * q + 1]);
        }
        *(uint2*)(g_F + (size_t)z * NE + i) = ov;
    }
}
__global__ void wchain_kernel(const float* __restrict__ wr) {
    size_t i = ((size_t)blockIdx.x * 256 + threadIdx.x) * 4;
    if (i >= NE) return;
    float4 w0 = *(const float4*)(wr + i);
    float w[4] = { w0.x, w0.y, w0.z, w0.w };
    #pragma unroll
    for (int z = 0; z < 5; z++) {
        uint2 gv = *(const uint2*)(g_GW + (size_t)z * NE + i);
        uint2 mv = *(const uint2*)(g_WM + (size_t)z * NE + i);
        const __half2* g2 = (const __half2*)&gv;
        const __half2* m2 = (const __half2*)&mv;
        #pragma unroll
        for (int q = 0; q < 2; q++) {
            float2 gq = __half22float2(g2[q]);
            float2 mq = __half22float2(m2[q]);
            w[2 * q]     += (mq.x - w[2 * q])     * gq.x;
            w[2 * q + 1] += (mq.y - w[2 * q + 1]) * gq.y;
        }
    }
    uint2 ov;
    __half2* o2 = (__half2*)&ov;
    o2[0].x = __float2half(w[0]); o2[0].y = __float2half(w[1]);
    o2[1].x = __float2half(w[2]); o2[1].y = __float2half(w[3]);
    *(uint2*)(g_W4 + i) = ov;
}

// ---------------- GEMM ----------------
#define MODE_PLAIN 0
#define MODE_SIG   2
#define MODE_EADD  4
#define MODE_MIX   5

// M=128 x N=128 CTA tile. smem per stage: A 16K + B 16K = 32K; 3 stages = 96K
#define SAH(s) ((s) * 32768)
#define SBB(s) ((s) * 32768 + 16384)
#define GEMM_SMEM 98304

template<int MODE>
__global__ void __launch_bounds__(256, 2) gemm_lm(GArg8 g, int K,
                                                  const float* __restrict__ e0f,
                                                  float* __restrict__ dout)
{
    extern __shared__ __align__(1024) char dsm[];
    const uint32_t sb = (uint32_t)__cvta_generic_to_shared(dsm);
    const int tid = threadIdx.x, lane = tid & 31, warp = tid >> 5;
    const int wm = warp >> 1, wn = warp & 1;
    const int bm = blockIdx.x, bn = blockIdx.y;
    const int z  = blockIdx.z;
    const int KT = K >> 6;

    const __half* a1p = g.a1[z] + (size_t)bm * 128 * 512;
    const __half* a2p = g.a2[z] + (size_t)bm * 128 * 512;
    const __half* Bb  = g.w[z]  + (size_t)bn * 128 * K;
    const float*  bias = g.bias[z];
    __half* out = g.out[z];
    const int zmode = (MODE == MODE_MIX) ? g.mode[z] : 0;

    float acc[2][8][4];
    #pragma unroll
    for (int i = 0; i < 2; i++)
        #pragma unroll
        for (int j = 0; j < 8; j++)
            #pragma unroll
            for (int q = 0; q < 4; q++) acc[i][j][q] = 0.f;

    auto load_stage = [&](int s, int kt) {
        const int k0 = kt << 6;
        const __half* base = (k0 < 512) ? (a1p + k0) : (a2p + (k0 - 512));
        #pragma unroll
        for (int i = 0; i < 4; i++) {
            const int id = tid + 256 * i;
            const int row = id >> 3, c = id & 7;
            const uint32_t sw = (row << 7) | ((c ^ (row & 7)) << 4);
            cp16s(sb + SAH(s) + sw, base + (size_t)row * 512 + c * 8);
            cp16s(sb + SBB(s) + sw, Bb + (size_t)row * K + k0 + c * 8);
        }
        asm volatile("cp.async.commit_group;");
    };

    load_stage(0, 0);
    load_stage(1, 1);

    const int lrow = lane & 15;
    const int lhi  = lane >> 4;
    const int lph  = lane & 7;
    const uint32_t aRow0 = (uint32_t)(wm * 32 + lrow) << 7;
    const uint32_t bRow0 = (uint32_t)(wn * 64 + lrow) << 7;

    int s = 0;
    for (int kt = 0; kt < KT; kt++) {
        if (kt + 2 < KT) {
            int s2 = s + 2; if (s2 >= 3) s2 -= 3;
            load_stage(s2, kt + 2);
            asm volatile("cp.async.wait_group 2;");
        } else if (kt + 1 < KT) {
            asm volatile("cp.async.wait_group 1;");
        } else {
            asm volatile("cp.async.wait_group 0;");
        }
        __syncthreads();
        const uint32_t aH = sb + SAH(s);
        const uint32_t bS = sb + SBB(s);

        #pragma unroll
        for (int kq = 0; kq < 4; kq++) {
            const uint32_t cb = (uint32_t)(((kq * 2 + lhi) ^ lph) << 4);
            uint32_t ah[2][4], b[4][4];
            #pragma unroll
            for (int mi = 0; mi < 2; mi++)
                ldmx4(aH + aRow0 + (uint32_t)(mi * 2048) + cb, ah[mi][0], ah[mi][1], ah[mi][2], ah[mi][3]);
            #pragma unroll
            for (int n2 = 0; n2 < 4; n2++)
                ldmx4(bS + bRow0 + (uint32_t)(n2 * 2048) + cb, b[n2][0], b[n2][1], b[n2][2], b[n2][3]);
            #pragma unroll
            for (int mi = 0; mi < 2; mi++)
                #pragma unroll
                for (int ni = 0; ni < 8; ni++)
                    MMA16(acc[mi][ni], ah[mi][0], ah[mi][1], ah[mi][2], ah[mi][3],
                          b[ni >> 1][ni & 1], b[ni >> 1][2 + (ni & 1)]);
        }
        __syncthreads();
        if (++s >= 3) s -= 3;
    }

    // ---------------- epilogue ----------------
    float jacc[4][3];
    const float* w2 = (MODE == MODE_MIX) ? g.w2[z] : nullptr;
    const int nz = (MODE == MODE_MIX) ? g.nout[z] : 0;
    if (MODE == MODE_MIX && zmode == 1) {
        #pragma unroll
        for (int rr = 0; rr < 4; rr++)
            #pragma unroll
            for (int j = 0; j < 3; j++) jacc[rr][j] = 0.f;
    }

    auto process = [&](int rr, int r, int c, float v0, float v1) {
        v0 += bias[c];
        v1 += bias[c + 1];
        if (MODE == MODE_SIG || (MODE == MODE_MIX && zmode == 0)) {
            v0 = 1.f / (1.f + expf(-v0));
            v1 = 1.f / (1.f + expf(-v1));
        } else if (MODE == MODE_MIX && zmode == 1) {
            v0 = 0.5f * v0 * (1.f + erff(v0 * 0.70710678118654752f));
            v1 = 0.5f * v1 * (1.f + erff(v1 * 0.70710678118654752f));
            #pragma unroll
            for (int j = 0; j < 3; j++)
                if (j < nz)
                    jacc[rr][j] += v0 * w2[c * nz + j] + v1 * w2[(c + 1) * nz + j];
            return;   // no store for head z's
        } else if (MODE == MODE_EADD) {
            float2 e2 = *(const float2*)(e0f + (size_t)r * 512 + c);
            v0 += e2.x;
            v1 += e2.y;
        }
        __half2 hh;
        hh.x = __float2half(v0);
        hh.y = __float2half(v1);
        *(__half2*)(out + (size_t)r * 512 + c) = hh;
    };

    #pragma unroll
    for (int mi = 0; mi < 2; mi++) {
        #pragma unroll
        for (int ni = 0; ni < 8; ni++) {
            const int r0 = bm * 128 + wm * 32 + mi * 16 + (lane >> 2);
            const int c  = bn * 128 + wn * 64 + ni * 8 + (lane & 3) * 2;
            process(mi * 2 + 0, r0,     c, acc[mi][ni][0], acc[mi][ni][1]);
            process(mi * 2 + 1, r0 + 8, c, acc[mi][ni][2], acc[mi][ni][3]);
        }
    }

    if (MODE == MODE_MIX && zmode == 1) {
        const int jb = g.jb[z];
        #pragma unroll
        for (int rr = 0; rr < 4; rr++) {
            const int row = bm * 128 + wm * 32 + (rr >> 1) * 16 + (rr & 1) * 8 + (lane >> 2);
            #pragma unroll
            for (int j = 0; j < 3; j++) {
                if (j < nz) {
                    float sval = jacc[rr][j];
                    sval += __shfl_xor_sync(0xffffffffu, sval, 1);
                    sval += __shfl_xor_sync(0xffffffffu, sval, 2);
                    if ((lane & 3) == 0)
                        atomicAdd(dout + (size_t)row * 7 + jb + j, sval);
                }
            }
        }
    }
}

// ---------------- host launch ----------------
extern "C" void kernel_launch(void* const* d_in, const int* in_sizes, int n_in,
                              void* d_out, int out_size) {
    (void)in_sizes; (void)n_in; (void)out_size;
    const float* sh    = (const float*)d_in[0];
    const float* el    = (const float*)d_in[1];
    const float* fa    = (const float*)d_in[2];
    const float* wr    = (const float*)d_in[3];
    const float* s2e_W = (const float*)d_in[4];
    const float* s2e_b = (const float*)d_in[5];
    const float* tf_W  = (const float*)d_in[6];
    const float* tf_b  = (const float*)d_in[7];
    const float* fw_W  = (const float*)d_in[8];
    const float* fw_b  = (const float*)d_in[9];
    const float* fg_W  = (const float*)d_in[10];
    const float* fg_b  = (const float*)d_in[11];
    const float* wg_W  = (const float*)d_in[12];
    const float* wg_b  = (const float*)d_in[13];
    const float* hsW1  = (const float*)d_in[14];
    const float* hsb1  = (const float*)d_in[15];
    const float* hsW2  = (const float*)d_in[16];
    const float* hsb2  = (const float*)d_in[17];
    const float* heW1  = (const float*)d_in[18];
    const float* heb1  = (const float*)d_in[19];
    const float* heW2  = (const float*)d_in[20];
    const float* heb2  = (const float*)d_in[21];
    const float* hfW1  = (const float*)d_in[22];
    const float* hfb1  = (const float*)d_in[23];
    const float* hfW2  = (const float*)d_in[24];
    const float* hfb2  = (const float*)d_in[25];
    const float* hwW1  = (const float*)d_in[26];
    const float* hwb1  = (const float*)d_in[27];
    const float* hwW2  = (const float*)d_in[28];
    const float* hwb2  = (const float*)d_in[29];

    __half *WP, *SH, *E, *FM, *GF, *F, *WM, *GW, *W4;
    float* CB;
    cudaGetSymbolAddress((void**)&WP,    g_WP);
    cudaGetSymbolAddress((void**)&CB,    g_CB);
    cudaGetSymbolAddress((void**)&SH,    g_SH);
    cudaGetSymbolAddress((void**)&E,     g_E);
    cudaGetSymbolAddress((void**)&FM,    g_FM);
    cudaGetSymbolAddress((void**)&GF,    g_GF);
    cudaGetSymbolAddress((void**)&F,     g_F);
    cudaGetSymbolAddress((void**)&WM,    g_WM);
    cudaGetSymbolAddress((void**)&GW,    g_GW);
    cudaGetSymbolAddress((void**)&W4,    g_W4);

    cudaFuncSetAttribute(gemm_lm<MODE_PLAIN>, cudaFuncAttributeMaxDynamicSharedMemorySize, GEMM_SMEM);
    cudaFuncSetAttribute(gemm_lm<MODE_SIG>,   cudaFuncAttributeMaxDynamicSharedMemorySize, GEMM_SMEM);
    cudaFuncSetAttribute(gemm_lm<MODE_EADD>,  cudaFuncAttributeMaxDynamicSharedMemorySize, GEMM_SMEM);
    cudaFuncSetAttribute(gemm_lm<MODE_MIX>,   cudaFuncAttributeMaxDynamicSharedMemorySize, GEMM_SMEM);

    const int EW4_GRID = (int)(NE / 1024);
    float* dout = (float*)d_out;

    // ---------------- setup ----------------
    split_sh_kernel<<<(int)(NE / 1024), 256>>>(sh);
    init_out_kernel<<<BATCH / 256, 256>>>(dout, hsb2, heb2, hfb2, hwb2);
    pack_cumsum<<<dim3(16, 16), 256>>>(s2e_W);
    cumbias_kernel<<<1, 512>>>(s2e_b);
    {
        PackAll j{};
        int n = 0;
        for (int i = 0; i < 5; i++) { j.src[n] = fg_W + (size_t)i * 512 * 512; j.dst[n] = FG_OFF + i * S2E_SZ; j.K[n] = 512;  j.xmask[n] = 0;   n++; }
        for (int i = 0; i < 5; i++) { j.src[n] = wg_W + (size_t)i * 512 * 512; j.dst[n] = WG_OFF + i * S2E_SZ; j.K[n] = 512;  j.xmask[n] = 0;   n++; }
        j.src[n] = hsW1; j.dst[n] = H1_OFF + 0 * S2E_SZ; j.K[n] = 512; j.xmask[n] = 0; n++;
        j.src[n] = heW1; j.dst[n] = H1_OFF + 1 * S2E_SZ; j.K[n] = 512; j.xmask[n] = 0; n++;
        j.src[n] = hfW1; j.dst[n] = H1_OFF + 2 * S2E_SZ; j.K[n] = 512; j.xmask[n] = 0; n++;
        j.src[n] = hwW1; j.dst[n] = H1_OFF + 3 * S2E_SZ; j.K[n] = 512; j.xmask[n] = 0; n++;
        for (int i = 0; i < 5; i++) { j.src[n] = tf_W + (size_t)i * 1024 * 512; j.dst[n] = TF_OFF + i * TF_SZ; j.K[n] = 1024; j.xmask[n] = 512; n++; }  // [e | sh]
        for (int i = 0; i < 5; i++) { j.src[n] = fw_W + (size_t)i * 1024 * 512; j.dst[n] = FW_OFF + i * TF_SZ; j.K[n] = 1024; j.xmask[n] = 0;   n++; }  // [e | f]
        pack_all<<<dim3(32, 16, 24), 256>>>(j);
    }

    dim3 g5(BATCH / 128, 4, 5);
    dim3 g8(BATCH / 128, 4, 8);
    dim3 g1(BATCH / 128, 4, 1);

    // ---------------- GEMM chain ----------------
    // A: e_z = e0 + sh @ Wc_z + bc_z
    {
        GArg8 a{};
        for (int z = 0; z < 5; z++) {
            a.a1[z] = SH; a.a2[z] = SH;
            a.w[z]  = WP + S2E_OFF + (size_t)z * S2E_SZ;
            a.bias[z] = CB + z * 512;
            a.out[z]  = E + (size_t)z * NE;
        }
        gemm_lm<MODE_EADD><<<g5, 256, GEMM_SMEM>>>(a, 512, el, nullptr);
    }
    // B: fm_z = [e_z | sh] @ tfW'_z + tf_b_z
    {
        GArg8 a{};
        for (int z = 0; z < 5; z++) {
            a.a1[z] = E + (size_t)z * NE; a.a2[z] = SH;
            a.w[z]  = WP + TF_OFF + (size_t)z * TF_SZ;
            a.bias[z] = tf_b + z * 512;
            a.out[z]  = FM + (size_t)z * NE;
        }
        gemm_lm<MODE_PLAIN><<<g5, 256, GEMM_SMEM>>>(a, 1024, nullptr, nullptr);
    }
    // C: gf_z = sigmoid(fm_z @ fgW_z + fg_b_z)
    {
        GArg8 a{};
        for (int z = 0; z < 5; z++) {
            a.a1[z] = FM + (size_t)z * NE; a.a2[z] = FM + (size_t)z * NE;
            a.w[z]  = WP + FG_OFF + (size_t)z * S2E_SZ;
            a.bias[z] = fg_b + z * 512;
            a.out[z]  = GF + (size_t)z * NE;
        }
        gemm_lm<MODE_SIG><<<g5, 256, GEMM_SMEM>>>(a, 512, nullptr, nullptr);
    }
    fchain_kernel<<<EW4_GRID, 256>>>(fa);
    // D: wm_z = [e_z | f_z] @ fwW_z + fw_b_z
    {
        GArg8 a{};
        for (int z = 0; z < 5; z++) {
            a.a1[z] = E + (size_t)z * NE; a.a2[z] = F + (size_t)z * NE;
            a.w[z]  = WP + FW_OFF + (size_t)z * TF_SZ;
            a.bias[z] = fw_b + z * 512;
            a.out[z]  = WM + (size_t)z * NE;
        }
        gemm_lm<MODE_PLAIN><<<g5, 256, GEMM_SMEM>>>(a, 1024, nullptr, nullptr);
    }
    // E + heads(sh,e,f): z0-4 sigmoid(wm@wgW) -> GW; z5-7 gelu head -> atomic out
    {
        GArg8 a{};
        for (int z = 0; z < 5; z++) {
            a.a1[z] = WM + (size_t)z * NE; a.a2[z] = WM + (size_t)z * NE;
            a.w[z]  = WP + WG_OFF + (size_t)z * S2E_SZ;
            a.bias[z] = wg_b + z * 512;
            a.out[z]  = GW + (size_t)z * NE;
            a.mode[z] = 0;
        }
        a.a1[5] = SH;         a.a2[5] = SH;         a.w[5] = WP + H1_OFF + 0 * S2E_SZ; a.bias[5] = hsb1; a.mode[5] = 1; a.w2[5] = hsW2; a.nout[5] = 3; a.jb[5] = 0;
        a.a1[6] = E + 4 * NE; a.a2[6] = E + 4 * NE; a.w[6] = WP + H1_OFF + 1 * S2E_SZ; a.bias[6] = heb1; a.mode[6] = 1; a.w2[6] = heW2; a.nout[6] = 1; a.jb[6] = 3;
        a.a1[7] = F + 4 * NE; a.a2[7] = F + 4 * NE; a.w[7] = WP + H1_OFF + 2 * S2E_SZ; a.bias[7] = hfb1; a.mode[7] = 1; a.w2[7] = hfW2; a.nout[7] = 1; a.jb[7] = 4;
        a.out[5] = GW; a.out[6] = GW; a.out[7] = GW;   // unused (guarded)
        gemm_lm<MODE_MIX><<<g8, 256, GEMM_SMEM>>>(a, 512, nullptr, dout);
    }
    wchain_kernel<<<EW4_GRID, 256>>>(wr);
    // hw head: gelu(w4 @ hwW1 + b) -> atomic out cols 5,6
    {
        GArg8 a{};
        a.a1[0] = W4; a.a2[0] = W4;
        a.w[0]  = WP + H1_OFF + 3 * S2E_SZ;
        a.bias[0] = hwb1;
        a.out[0]  = GW;   // unused (guarded)
        a.mode[0] = 1;
        a.w2[0] = hwW2; a.nout[0] = 2; a.jb[0] = 5;
        gemm_lm<MODE_MIX><<<g1, 256, GEMM_SMEM>>>(a, 512, nullptr, dout);
    }
}

// round 17
// speedup vs baseline: 2.0457x; 1.0106x over previous
#include <cuda_runtime.h>
#include <cuda_fp16.h>
#include <cstdint>
#include <cmath>

#define BATCH 32768
#define NE ((size_t)BATCH * 512)

// ---------------- packed weights ----------------
#define S2E_SZ (512*512)
#define TF_SZ  (512*1024)
#define S2E_OFF 0
#define TF_OFF  (S2E_OFF + 5*S2E_SZ)
#define FG_OFF  (TF_OFF  + 5*TF_SZ)
#define FW_OFF  (FG_OFF  + 5*S2E_SZ)
#define WG_OFF  (FW_OFF  + 5*TF_SZ)
#define H1_OFF  (WG_OFF  + 5*S2E_SZ)
#define WP_TOTAL (H1_OFF + 4*S2E_SZ)

__device__ __half g_WP[WP_TOTAL];
__device__ float  g_CB[5 * 512];
__device__ __half g_SH[NE];
__device__ __half g_E[5 * NE];
__device__ __half g_FM[5 * NE];
__device__ __half g_GF[5 * NE];
__device__ __half g_F[5 * NE];
__device__ __half g_WM[5 * NE];
__device__ __half g_GW[5 * NE];
__device__ __half g_W4[NE];

struct PackAll { const float* src[24]; unsigned dst[24]; int K[24]; int xmask[24]; };
struct GArg8 {
    const __half* a1[8];
    const __half* a2[8];
    const __half* w[8];
    const float*  bias[8];
    __half*       out[8];
    int           mode[8];   // MIX: 0=sigmoid->store, 1=gelu->head reduction
    const float*  w2[8];
    int           nout[8];
    int           jb[8];
};

// ---------------- helpers ----------------
__device__ __forceinline__ void cp16s(uint32_t sa, const void* g) {
    asm volatile("cp.async.cg.shared.global [%0], [%1], 16;" :: "r"(sa), "l"(g));
}
__device__ __forceinline__ void ldmx4(uint32_t addr, uint32_t& r0, uint32_t& r1, uint32_t& r2, uint32_t& r3) {
    asm volatile("ldmatrix.sync.aligned.m8n8.x4.shared.b16 {%0,%1,%2,%3}, [%4];"
        : "=r"(r0), "=r"(r1), "=r"(r2), "=r"(r3) : "r"(addr));
}
#define MMA16(acc, a0,a1,a2,a3, b0,b1) \
    asm volatile("mma.sync.aligned.m16n8k16.row.col.f32.f16.f16.f32 " \
        "{%0,%1,%2,%3},{%4,%5,%6,%7},{%8,%9},{%0,%1,%2,%3};" \
        : "+f"((acc)[0]), "+f"((acc)[1]), "+f"((acc)[2]), "+f"((acc)[3]) \
        : "r"(a0), "r"(a1), "r"(a2), "r"(a3), "r"(b0), "r"(b1))

// ---------------- setup kernels ----------------
__global__ void split_sh_kernel(const float* __restrict__ sh) {
    size_t i = ((size_t)blockIdx.x * 256 + threadIdx.x) * 4;
    if (i >= NE) return;
    float4 v = *(const float4*)(sh + i);
    __half2 a, b;
    a.x = __float2half(v.x); a.y = __float2half(v.y);
    b.x = __float2half(v.z); b.y = __float2half(v.w);
    *(__half2*)(g_SH + i)     = a;
    *(__half2*)(g_SH + i + 2) = b;
}

__global__ void init_out_kernel(float* __restrict__ out,
    const float* __restrict__ b0, const float* __restrict__ b1,
    const float* __restrict__ b2, const float* __restrict__ b3) {
    int r = blockIdx.x * 256 + threadIdx.x;
    if (r >= BATCH) return;
    float* o = out + (size_t)r * 7;
    o[0] = b0[0]; o[1] = b0[1]; o[2] = b0[2];
    o[3] = b1[0]; o[4] = b2[0];
    o[5] = b3[0]; o[6] = b3[1];
}

__global__ void pack_all(PackAll job) {
    __shared__ float t[32][33];
    const int j = blockIdx.z;
    const int K = job.K[j];
    const int k0 = blockIdx.x * 32;
    if (k0 >= K) return;
    const int n0 = blockIdx.y * 32;
    const int xmask = job.xmask[j];
    const float* Wl = job.src[j];
    __half* ol = g_WP + job.dst[j];
    int r = threadIdx.x >> 5, c = threadIdx.x & 31;
    #pragma unroll
    for (int i = 0; i < 4; i++)
        t[r + 8 * i][c] = Wl[(size_t)(k0 + r + 8 * i) * 512 + n0 + c];
    __syncthreads();
    #pragma unroll
    for (int i = 0; i < 4; i++) {
        int n = n0 + r + 8 * i;
        ol[(size_t)n * K + ((k0 + c) ^ xmask)] = __float2half(t[c][r + 8 * i]);
    }
}

__global__ void pack_cumsum(const float* __restrict__ W) {
    __shared__ float t[32][33];
    int k0 = blockIdx.x * 32, n0 = blockIdx.y * 32;
    int r = threadIdx.x >> 5, c = threadIdx.x & 31;
    float acc[4] = {0.f, 0.f, 0.f, 0.f};
    for (int z = 0; z < 5; z++) {
        const float* Wl = W + (size_t)z * 512 * 512;
        #pragma unroll
        for (int i = 0; i < 4; i++)
            t[r + 8 * i][c] = Wl[(size_t)(k0 + r + 8 * i) * 512 + n0 + c];
        __syncthreads();
        #pragma unroll
        for (int i = 0; i < 4; i++) {
            acc[i] += t[c][r + 8 * i];
            int n = n0 + r + 8 * i;
            g_WP[S2E_OFF + (size_t)z * S2E_SZ + (size_t)n * 512 + k0 + c] = __float2half(acc[i]);
        }
        __syncthreads();
    }
}

__global__ void cumbias_kernel(const float* __restrict__ b) {
    int j = threadIdx.x;
    float s = 0.f;
    for (int z = 0; z < 5; z++) {
        s += b[z * 512 + j];
        g_CB[z * 512 + j] = s;
    }
}

// ---------------- elementwise chains ----------------
__global__ void fchain_kernel(const float* __restrict__ fa) {
    size_t i = ((size_t)blockIdx.x * 256 + threadIdx.x) * 4;
    if (i >= NE) return;
    float4 f0 = *(const float4*)(fa + i);
    float f[4] = { f0.x, f0.y, f0.z, f0.w };
    #pragma unroll
    for (int z = 0; z < 5; z++) {
        uint2 gv = *(const uint2*)(g_GF + (size_t)z * NE + i);
        uint2 mv = *(const uint2*)(g_FM + (size_t)z * NE + i);
        const __half2* g2 = (const __half2*)&gv;
        const __half2* m2 = (const __half2*)&mv;
        uint2 ov;
        __half2* o2 = (__half2*)&ov;
        #pragma unroll
        for (int q = 0; q < 2; q++) {
            float2 gq = __half22float2(g2[q]);
            float2 mq = __half22float2(m2[q]);
            f[2 * q]     += (mq.x - f[2 * q])     * gq.x;
            f[2 * q + 1] += (mq.y - f[2 * q + 1]) * gq.y;
            o2[q].x = __float2half(f[2 * q]);
            o2[q].y = __float2half(f[2 * q + 1]);
        }
        *(uint2*)(g_F + (size_t)z * NE + i) = ov;
    }
}
__global__ void wchain_kernel(const float* __restrict__ wr) {
    size_t i = ((size_t)blockIdx.x * 256 + threadIdx.x) * 4;
    if (i >= NE) return;
    float4 w0 = *(const float4*)(wr + i);
    float w[4] = { w0.x, w0.y, w0.z, w0.w };
    #pragma unroll
    for (int z = 0; z < 5; z++) {
        uint2 gv = *(const uint2*)(g_GW + (size_t)z * NE + i);
        uint2 mv = *(const uint2*)(g_WM + (size_t)z * NE + i);
        const __half2* g2 = (const __half2*)&gv;
        const __half2* m2 = (const __half2*)&mv;
        #pragma unroll
        for (int q = 0; q < 2; q++) {
            float2 gq = __half22float2(g2[q]);
            float2 mq = __half22float2(m2[q]);
            w[2 * q]     += (mq.x - w[2 * q])     * gq.x;
            w[2 * q + 1] += (mq.y - w[2 * q + 1]) * gq.y;
        }
    }
    uint2 ov;
    __half2* o2 = (__half2*)&ov;
    o2[0].x = __float2half(w[0]); o2[0].y = __float2half(w[1]);
    o2[1].x = __float2half(w[2]); o2[1].y = __float2half(w[3]);
    *(uint2*)(g_W4 + i) = ov;
}

// ---------------- GEMM ----------------
#define MODE_PLAIN 0
#define MODE_SIG   2
#define MODE_EADD  4
#define MODE_MIX   5

#define SAH(s) ((s) * 32768)
#define SBB(s) ((s) * 32768 + 16384)
#define GEMM_SMEM 98304

template<int MODE>
__global__ void __launch_bounds__(256, 2) gemm_lm(GArg8 g, int K,
                                                  const float* __restrict__ e0f,
                                                  float* __restrict__ dout)
{
    extern __shared__ __align__(1024) char dsm[];
    const uint32_t sb = (uint32_t)__cvta_generic_to_shared(dsm);
    const int tid = threadIdx.x, lane = tid & 31, warp = tid >> 5;
    const int wm = warp >> 1, wn = warp & 1;
    const int bm = blockIdx.x, bn = blockIdx.y;
    const int z  = blockIdx.z;
    const int KT = K >> 6;

    const __half* a1p = g.a1[z] + (size_t)bm * 128 * 512;
    const __half* a2p = g.a2[z] + (size_t)bm * 128 * 512;
    const __half* Bb  = g.w[z]  + (size_t)bn * 128 * K;
    const float*  bias = g.bias[z];
    __half* out = g.out[z];
    const int zmode = (MODE == MODE_MIX) ? g.mode[z] : 0;

    float acc[2][8][4];
    #pragma unroll
    for (int i = 0; i < 2; i++)
        #pragma unroll
        for (int j = 0; j < 8; j++)
            #pragma unroll
            for (int q = 0; q < 4; q++) acc[i][j][q] = 0.f;

    auto load_stage = [&](int s, int kt) {
        const int k0 = kt << 6;
        const __half* base = (k0 < 512) ? (a1p + k0) : (a2p + (k0 - 512));
        #pragma unroll
        for (int i = 0; i < 4; i++) {
            const int id = tid + 256 * i;
            const int row = id >> 3, c = id & 7;
            const uint32_t sw = (row << 7) | ((c ^ (row & 7)) << 4);
            cp16s(sb + SAH(s) + sw, base + (size_t)row * 512 + c * 8);
            cp16s(sb + SBB(s) + sw, Bb + (size_t)row * K + k0 + c * 8);
        }
        asm volatile("cp.async.commit_group;");
    };

    load_stage(0, 0);
    load_stage(1, 1);

    const int lrow = lane & 15;
    const int lhi  = lane >> 4;
    const int lph  = lane & 7;
    const uint32_t aRow0 = (uint32_t)(wm * 32 + lrow) << 7;
    const uint32_t bRow0 = (uint32_t)(wn * 64 + lrow) << 7;

    int s = 0;
    for (int kt = 0; kt < KT; kt++) {
        if (kt + 2 < KT) {
            int s2 = s + 2; if (s2 >= 3) s2 -= 3;
            load_stage(s2, kt + 2);
            asm volatile("cp.async.wait_group 2;");
        } else if (kt + 1 < KT) {
            asm volatile("cp.async.wait_group 1;");
        } else {
            asm volatile("cp.async.wait_group 0;");
        }
        __syncthreads();
        const uint32_t aH = sb + SAH(s);
        const uint32_t bS = sb + SBB(s);

        #pragma unroll
        for (int kq = 0; kq < 4; kq++) {
            const uint32_t cb = (uint32_t)(((kq * 2 + lhi) ^ lph) << 4);
            uint32_t ah[2][4], b[4][4];
            #pragma unroll
            for (int mi = 0; mi < 2; mi++)
                ldmx4(aH + aRow0 + (uint32_t)(mi * 2048) + cb, ah[mi][0], ah[mi][1], ah[mi][2], ah[mi][3]);
            #pragma unroll
            for (int n2 = 0; n2 < 4; n2++)
                ldmx4(bS + bRow0 + (uint32_t)(n2 * 2048) + cb, b[n2][0], b[n2][1], b[n2][2], b[n2][3]);
            #pragma unroll
            for (int mi = 0; mi < 2; mi++)
                #pragma unroll
                for (int ni = 0; ni < 8; ni++)
                    MMA16(acc[mi][ni], ah[mi][0], ah[mi][1], ah[mi][2], ah[mi][3],
                          b[ni >> 1][ni & 1], b[ni >> 1][2 + (ni & 1)]);
        }
        __syncthreads();
        if (++s >= 3) s -= 3;
    }

    // ---------------- epilogue ----------------
    float jacc[4][3];
    const float* w2 = (MODE == MODE_MIX) ? g.w2[z] : nullptr;
    const int nz = (MODE == MODE_MIX) ? g.nout[z] : 0;
    if (MODE == MODE_MIX && zmode == 1) {
        #pragma unroll
        for (int rr = 0; rr < 4; rr++)
            #pragma unroll
            for (int j = 0; j < 3; j++) jacc[rr][j] = 0.f;
    }

    auto process = [&](int rr, int r, int c, float v0, float v1) {
        v0 += bias[c];
        v1 += bias[c + 1];
        if (MODE == MODE_SIG || (MODE == MODE_MIX && zmode == 0)) {
            v0 = 1.f / (1.f + expf(-v0));
            v1 = 1.f / (1.f + expf(-v1));
        } else if (MODE == MODE_MIX && zmode == 1) {
            v0 = 0.5f * v0 * (1.f + erff(v0 * 0.70710678118654752f));
            v1 = 0.5f * v1 * (1.f + erff(v1 * 0.70710678118654752f));
            #pragma unroll
            for (int j = 0; j < 3; j++)
                if (j < nz)
                    jacc[rr][j] += v0 * w2[c * nz + j] + v1 * w2[(c + 1) * nz + j];
            return;
        } else if (MODE == MODE_EADD) {
            float2 e2 = *(const float2*)(e0f + (size_t)r * 512 + c);
            v0 += e2.x;
            v1 += e2.y;
        }
        __half2 hh;
        hh.x = __float2half(v0);
        hh.y = __float2half(v1);
        *(__half2*)(out + (size_t)r * 512 + c) = hh;
    };

    #pragma unroll
    for (int mi = 0; mi < 2; mi++) {
        #pragma unroll
        for (int ni = 0; ni < 8; ni++) {
            const int r0 = bm * 128 + wm * 32 + mi * 16 + (lane >> 2);
            const int c  = bn * 128 + wn * 64 + ni * 8 + (lane & 3) * 2;
            process(mi * 2 + 0, r0,     c, acc[mi][ni][0], acc[mi][ni][1]);
            process(mi * 2 + 1, r0 + 8, c, acc[mi][ni][2], acc[mi][ni][3]);
        }
    }

    if (MODE == MODE_MIX && zmode == 1) {
        const int jb = g.jb[z];
        #pragma unroll
        for (int rr = 0; rr < 4; rr++) {
            const int row = bm * 128 + wm * 32 + (rr >> 1) * 16 + (rr & 1) * 8 + (lane >> 2);
            #pragma unroll
            for (int j = 0; j < 3; j++) {
                if (j < nz) {
                    float sval = jacc[rr][j];
                    sval += __shfl_xor_sync(0xffffffffu, sval, 1);
                    sval += __shfl_xor_sync(0xffffffffu, sval, 2);
                    if ((lane & 3) == 0)
                        atomicAdd(dout + (size_t)row * 7 + jb + j, sval);
                }
            }
        }
    }
}

// ---------------- host launch ----------------
extern "C" void kernel_launch(void* const* d_in, const int* in_sizes, int n_in,
                              void* d_out, int out_size) {
    (void)in_sizes; (void)n_in; (void)out_size;
    const float* sh    = (const float*)d_in[0];
    const float* el    = (const float*)d_in[1];
    const float* fa    = (const float*)d_in[2];
    const float* wr    = (const float*)d_in[3];
    const float* s2e_W = (const float*)d_in[4];
    const float* s2e_b = (const float*)d_in[5];
    const float* tf_W  = (const float*)d_in[6];
    const float* tf_b  = (const float*)d_in[7];
    const float* fw_W  = (const float*)d_in[8];
    const float* fw_b  = (const float*)d_in[9];
    const float* fg_W  = (const float*)d_in[10];
    const float* fg_b  = (const float*)d_in[11];
    const float* wg_W  = (const float*)d_in[12];
    const float* wg_b  = (const float*)d_in[13];
    const float* hsW1  = (const float*)d_in[14];
    const float* hsb1  = (const float*)d_in[15];
    const float* hsW2  = (const float*)d_in[16];
    const float* hsb2  = (const float*)d_in[17];
    const float* heW1  = (const float*)d_in[18];
    const float* heb1  = (const float*)d_in[19];
    const float* heW2  = (const float*)d_in[20];
    const float* heb2  = (const float*)d_in[21];
    const float* hfW1  = (const float*)d_in[22];
    const float* hfb1  = (const float*)d_in[23];
    const float* hfW2  = (const float*)d_in[24];
    const float* hfb2  = (const float*)d_in[25];
    const float* hwW1  = (const float*)d_in[26];
    const float* hwb1  = (const float*)d_in[27];
    const float* hwW2  = (const float*)d_in[28];
    const float* hwb2  = (const float*)d_in[29];

    __half *WP, *SH, *E, *FM, *GF, *F, *WM, *GW, *W4;
    float* CB;
    cudaGetSymbolAddress((void**)&WP,    g_WP);
    cudaGetSymbolAddress((void**)&CB,    g_CB);
    cudaGetSymbolAddress((void**)&SH,    g_SH);
    cudaGetSymbolAddress((void**)&E,     g_E);
    cudaGetSymbolAddress((void**)&FM,    g_FM);
    cudaGetSymbolAddress((void**)&GF,    g_GF);
    cudaGetSymbolAddress((void**)&F,     g_F);
    cudaGetSymbolAddress((void**)&WM,    g_WM);
    cudaGetSymbolAddress((void**)&GW,    g_GW);
    cudaGetSymbolAddress((void**)&W4,    g_W4);

    static bool s_init = false;
    static cudaStream_t s2;
    static cudaEvent_t ev1, ev2, ev3, ev4;
    if (!s_init) {
        cudaStreamCreateWithFlags(&s2, cudaStreamNonBlocking);
        cudaEventCreateWithFlags(&ev1, cudaEventDisableTiming);
        cudaEventCreateWithFlags(&ev2, cudaEventDisableTiming);
        cudaEventCreateWithFlags(&ev3, cudaEventDisableTiming);
        cudaEventCreateWithFlags(&ev4, cudaEventDisableTiming);
        cudaFuncSetAttribute(gemm_lm<MODE_PLAIN>, cudaFuncAttributeMaxDynamicSharedMemorySize, GEMM_SMEM);
        cudaFuncSetAttribute(gemm_lm<MODE_SIG>,   cudaFuncAttributeMaxDynamicSharedMemorySize, GEMM_SMEM);
        cudaFuncSetAttribute(gemm_lm<MODE_EADD>,  cudaFuncAttributeMaxDynamicSharedMemorySize, GEMM_SMEM);
        cudaFuncSetAttribute(gemm_lm<MODE_MIX>,   cudaFuncAttributeMaxDynamicSharedMemorySize, GEMM_SMEM);
        s_init = true;
    }

    const int EW4_GRID = (int)(NE / 1024);
    float* dout = (float*)d_out;

    // ---------------- setup (deps of GEMM A on main stream) ----------------
    split_sh_kernel<<<(int)(NE / 1024), 256>>>(sh);
    pack_cumsum<<<dim3(16, 16), 256>>>(s2e_W);
    cumbias_kernel<<<1, 512>>>(s2e_b);

    // fork: pack_all + init_out on side stream, parallel with GEMM A
    cudaEventRecord(ev1, 0);
    cudaStreamWaitEvent(s2, ev1, 0);
    {
        PackAll j{};
        int n = 0;
        for (int i = 0; i < 5; i++) { j.src[n] = fg_W + (size_t)i * 512 * 512; j.dst[n] = FG_OFF + i * S2E_SZ; j.K[n] = 512;  j.xmask[n] = 0;   n++; }
        for (int i = 0; i < 5; i++) { j.src[n] = wg_W + (size_t)i * 512 * 512; j.dst[n] = WG_OFF + i * S2E_SZ; j.K[n] = 512;  j.xmask[n] = 0;   n++; }
        j.src[n] = hsW1; j.dst[n] = H1_OFF + 0 * S2E_SZ; j.K[n] = 512; j.xmask[n] = 0; n++;
        j.src[n] = heW1; j.dst[n] = H1_OFF + 1 * S2E_SZ; j.K[n] = 512; j.xmask[n] = 0; n++;
        j.src[n] = hfW1; j.dst[n] = H1_OFF + 2 * S2E_SZ; j.K[n] = 512; j.xmask[n] = 0; n++;
        j.src[n] = hwW1; j.dst[n] = H1_OFF + 3 * S2E_SZ; j.K[n] = 512; j.xmask[n] = 0; n++;
        for (int i = 0; i < 5; i++) { j.src[n] = tf_W + (size_t)i * 1024 * 512; j.dst[n] = TF_OFF + i * TF_SZ; j.K[n] = 1024; j.xmask[n] = 512; n++; }
        for (int i = 0; i < 5; i++) { j.src[n] = fw_W + (size_t)i * 1024 * 512; j.dst[n] = FW_OFF + i * TF_SZ; j.K[n] = 1024; j.xmask[n] = 0;   n++; }
        pack_all<<<dim3(32, 16, 24), 256, 0, s2>>>(j);
    }
    init_out_kernel<<<BATCH / 256, 256, 0, s2>>>(dout, hsb2, heb2, hfb2, hwb2);
    cudaEventRecord(ev2, s2);

    dim3 g5(BATCH / 128, 4, 5);
    dim3 g3(BATCH / 128, 4, 3);
    dim3 g1(BATCH / 128, 4, 1);

    // A: e_z = e0 + sh @ Wc_z + bc_z   (main, parallel with pack_all)
    {
        GArg8 a{};
        for (int z = 0; z < 5; z++) {
            a.a1[z] = SH; a.a2[z] = SH;
            a.w[z]  = WP + S2E_OFF + (size_t)z * S2E_SZ;
            a.bias[z] = CB + z * 512;
            a.out[z]  = E + (size_t)z * NE;
        }
        gemm_lm<MODE_EADD><<<g5, 256, GEMM_SMEM>>>(a, 512, el, nullptr);
    }
    cudaStreamWaitEvent(0, ev2, 0);   // join: B needs tf pack

    // B: fm_z = [e_z | sh] @ tfW'_z + tf_b_z
    {
        GArg8 a{};
        for (int z = 0; z < 5; z++) {
            a.a1[z] = E + (size_t)z * NE; a.a2[z] = SH;
            a.w[z]  = WP + TF_OFF + (size_t)z * TF_SZ;
            a.bias[z] = tf_b + z * 512;
            a.out[z]  = FM + (size_t)z * NE;
        }
        gemm_lm<MODE_PLAIN><<<g5, 256, GEMM_SMEM>>>(a, 1024, nullptr, nullptr);
    }
    // C: gf_z = sigmoid(fm_z @ fgW_z + fg_b_z)
    {
        GArg8 a{};
        for (int z = 0; z < 5; z++) {
            a.a1[z] = FM + (size_t)z * NE; a.a2[z] = FM + (size_t)z * NE;
            a.w[z]  = WP + FG_OFF + (size_t)z * S2E_SZ;
            a.bias[z] = fg_b + z * 512;
            a.out[z]  = GF + (size_t)z * NE;
        }
        gemm_lm<MODE_SIG><<<g5, 256, GEMM_SMEM>>>(a, 512, nullptr, nullptr);
    }
    fchain_kernel<<<EW4_GRID, 256>>>(fa);
    // D: wm_z = [e_z | f_z] @ fwW_z + fw_b_z
    {
        GArg8 a{};
        for (int z = 0; z < 5; z++) {
            a.a1[z] = E + (size_t)z * NE; a.a2[z] = F + (size_t)z * NE;
            a.w[z]  = WP + FW_OFF + (size_t)z * TF_SZ;
            a.bias[z] = fw_b + z * 512;
            a.out[z]  = WM + (size_t)z * NE;
        }
        gemm_lm<MODE_PLAIN><<<g5, 256, GEMM_SMEM>>>(a, 1024, nullptr, nullptr);
    }
    // E: gates gw_z = sigmoid(wm_z @ wgW_z + wg_b_z)
    {
        GArg8 a{};
        for (int z = 0; z < 5; z++) {
            a.a1[z] = WM + (size_t)z * NE; a.a2[z] = WM + (size_t)z * NE;
            a.w[z]  = WP + WG_OFF + (size_t)z * S2E_SZ;
            a.bias[z] = wg_b + z * 512;
            a.out[z]  = GW + (size_t)z * NE;
        }
        gemm_lm<MODE_SIG><<<g5, 256, GEMM_SMEM>>>(a, 512, nullptr, nullptr);
    }

    // fork: heads sh/e/f on side stream, parallel with wchain + hw head
    cudaEventRecord(ev3, 0);
    cudaStreamWaitEvent(s2, ev3, 0);
    {
        GArg8 a{};
        a.a1[0] = SH;         a.a2[0] = SH;         a.w[0] = WP + H1_OFF + 0 * S2E_SZ; a.bias[0] = hsb1; a.mode[0] = 1; a.w2[0] = hsW2; a.nout[0] = 3; a.jb[0] = 0;
        a.a1[1] = E + 4 * NE; a.a2[1] = E + 4 * NE; a.w[1] = WP + H1_OFF + 1 * S2E_SZ; a.bias[1] = heb1; a.mode[1] = 1; a.w2[1] = heW2; a.nout[1] = 1; a.jb[1] = 3;
        a.a1[2] = F + 4 * NE; a.a2[2] = F + 4 * NE; a.w[2] = WP + H1_OFF + 2 * S2E_SZ; a.bias[2] = hfb1; a.mode[2] = 1; a.w2[2] = hfW2; a.nout[2] = 1; a.jb[2] = 4;
        a.out[0] = GW; a.out[1] = GW; a.out[2] = GW;   // unused (guarded)
        gemm_lm<MODE_MIX><<<g3, 256, GEMM_SMEM, s2>>>(a, 512, nullptr, dout);
    }
    cudaEventRecord(ev4, s2);

    // main: wchain -> hw head
    wchain_kernel<<<EW4_GRID, 256>>>(wr);
    {
        GArg8 a{};
        a.a1[0] = W4; a.a2[0] = W4;
        a.w[0]  = WP + H1_OFF + 3 * S2E_SZ;
        a.bias[0] = hwb1;
        a.out[0]  = GW;   // unused (guarded)
        a.mode[0] = 1;
        a.w2[0] = hwW2; a.nout[0] = 2; a.jb[0] = 5;
        gemm_lm<MODE_MIX><<<g1, 256, GEMM_SMEM>>>(a, 512, nullptr, dout);
    }
    cudaStreamWaitEvent(0, ev4, 0);   // join
}